// round 7
// baseline (speedup 1.0000x reference)
#include <cuda_runtime.h>
#include <cuda_bf16.h>
#include <cuda_fp16.h>
#include <math.h>
#include <stdint.h>

#define BATCH   1024
#define D_MODEL 4096
#define D_STATE 16
#define DT_RANK 256
#define XP_COLS (DT_RANK + 2 * D_STATE)   // 288
#define WXP_PAD 384                        // 288 padded to 3 x 128

// ---------------- scratch (allocation-free rule: __device__ globals) --------
__device__ float g_xp[BATCH * XP_COLS];
__device__ uint16_t g_Wh16[(size_t)D_MODEL * D_MODEL];   // fp16(W_out)
__device__ uint16_t g_Yh[(size_t)BATCH * D_MODEL];       // fp16(ypre)
__device__ uint16_t g_xh[(size_t)BATCH * D_MODEL];       // bf16 hi(x)
__device__ uint16_t g_xl[(size_t)BATCH * D_MODEL];       // bf16 lo(x)
__device__ uint16_t g_Wxh[(size_t)WXP_PAD * D_MODEL];    // bf16 hi(W_xproj), padded
__device__ uint16_t g_Wxl[(size_t)WXP_PAD * D_MODEL];
__device__ uint16_t g_dh[(size_t)BATCH * DT_RANK];       // bf16 hi(delta_raw)
__device__ uint16_t g_dl[(size_t)BATCH * DT_RANK];
__device__ uint16_t g_Wdh[(size_t)D_MODEL * DT_RANK];    // bf16 hi(W_dt)
__device__ uint16_t g_Wdl[(size_t)D_MODEL * DT_RANK];

__device__ __forceinline__ float softplusf(float z) {
    return (z > 20.0f) ? z : log1pf(__expf(z));
}

// ---------------- PTX helpers (sm_80-class only; no 'a'-target features) ----
__device__ __forceinline__ uint32_t smem_u32(const void* p) {
    uint32_t a;
    asm("{ .reg .u64 t; cvta.to.shared.u64 t, %1; cvt.u32.u64 %0, t; }" : "=r"(a) : "l"(p));
    return a;
}
__device__ __forceinline__ void cpasync16(uint32_t dst, const void* src) {
    asm volatile("cp.async.cg.shared.global [%0], [%1], 16;" :: "r"(dst), "l"(src));
}
__device__ __forceinline__ void cpasync_commit() {
    asm volatile("cp.async.commit_group;" ::: "memory");
}
__device__ __forceinline__ void ldmatrix_x4(uint32_t* r, uint32_t addr) {
    asm volatile("ldmatrix.sync.aligned.m8n8.x4.shared.b16 {%0,%1,%2,%3}, [%4];"
                 : "=r"(r[0]), "=r"(r[1]), "=r"(r[2]), "=r"(r[3]) : "r"(addr));
}
// DT: 0 = bf16, 1 = fp16
template<int DT>
__device__ __forceinline__ void mma16(float* c, const uint32_t* a, const uint32_t* b) {
    if constexpr (DT == 0) {
        asm volatile(
            "mma.sync.aligned.m16n8k16.row.col.f32.bf16.bf16.f32 "
            "{%0,%1,%2,%3}, {%4,%5,%6,%7}, {%8,%9}, {%0,%1,%2,%3};"
            : "+f"(c[0]), "+f"(c[1]), "+f"(c[2]), "+f"(c[3])
            : "r"(a[0]), "r"(a[1]), "r"(a[2]), "r"(a[3]), "r"(b[0]), "r"(b[1]));
    } else {
        asm volatile(
            "mma.sync.aligned.m16n8k16.row.col.f32.f16.f16.f32 "
            "{%0,%1,%2,%3}, {%4,%5,%6,%7}, {%8,%9}, {%0,%1,%2,%3};"
            : "+f"(c[0]), "+f"(c[1]), "+f"(c[2]), "+f"(c[3])
            : "r"(a[0]), "r"(a[1]), "r"(a[2]), "r"(a[3]), "r"(b[0]), "r"(b[1]));
    }
}

// ---------------------------------------------------------------------------
// Merged preparation kernel: one launch covers
//   [0]      W_out  -> fp16                (4,194,304 float4 slots)
//   [n0]     x      -> bf16 hi/lo          (1,048,576)
//   [n0+n1]  W_xproj-> bf16 hi/lo padded   (  393,216)
//   [..+n2]  W_dt   -> bf16 hi/lo          (  262,144)
//   [..+n3]  zero g_xp                     (   73,728)
// Total 5,971,968 slots = 23328 blocks x 256 exactly.
// ---------------------------------------------------------------------------
#define PREP_N0 ((size_t)D_MODEL * D_MODEL / 4)
#define PREP_N1 ((size_t)BATCH * D_MODEL / 4)
#define PREP_N2 ((size_t)WXP_PAD * D_MODEL / 4)
#define PREP_N3 ((size_t)D_MODEL * DT_RANK / 4)
#define PREP_N4 ((size_t)BATCH * XP_COLS / 4)
#define PREP_TOT (PREP_N0 + PREP_N1 + PREP_N2 + PREP_N3 + PREP_N4)

__device__ __forceinline__ void split4_bf16(const float* vv, uint16_t* h, uint16_t* l, size_t i) {
    #pragma unroll
    for (int q = 0; q < 4; q++) {
        __nv_bfloat16 hi = __float2bfloat16(vv[q]);
        __nv_bfloat16 lo = __float2bfloat16(vv[q] - __bfloat162float(hi));
        h[i + q] = *(uint16_t*)&hi;
        l[i + q] = *(uint16_t*)&lo;
    }
}

__global__ void __launch_bounds__(256)
prep_all(const float* __restrict__ Wout, const float* __restrict__ x,
         const float* __restrict__ Wxp, const float* __restrict__ Wdt)
{
    size_t gid = (size_t)blockIdx.x * 256 + threadIdx.x;
    if (gid < PREP_N0) {
        size_t i = gid * 4;
        float4 v = *(const float4*)(Wout + i);
        __half h0 = __float2half_rn(v.x), h1 = __float2half_rn(v.y);
        __half h2 = __float2half_rn(v.z), h3 = __float2half_rn(v.w);
        uint16_t* o = g_Wh16 + i;
        o[0] = *(uint16_t*)&h0; o[1] = *(uint16_t*)&h1;
        o[2] = *(uint16_t*)&h2; o[3] = *(uint16_t*)&h3;
    } else if (gid < PREP_N0 + PREP_N1) {
        size_t i = (gid - PREP_N0) * 4;
        float4 v = *(const float4*)(x + i);
        float vv[4] = {v.x, v.y, v.z, v.w};
        split4_bf16(vv, g_xh, g_xl, i);
    } else if (gid < PREP_N0 + PREP_N1 + PREP_N2) {
        size_t i = (gid - PREP_N0 - PREP_N1) * 4;
        int row = (int)(i >> 12);
        float vv[4] = {0.f, 0.f, 0.f, 0.f};
        if (row < XP_COLS) {
            float4 v = *(const float4*)(Wxp + i);
            vv[0] = v.x; vv[1] = v.y; vv[2] = v.z; vv[3] = v.w;
        }
        split4_bf16(vv, g_Wxh, g_Wxl, i);
    } else if (gid < PREP_N0 + PREP_N1 + PREP_N2 + PREP_N3) {
        size_t i = (gid - PREP_N0 - PREP_N1 - PREP_N2) * 4;
        float4 v = *(const float4*)(Wdt + i);
        float vv[4] = {v.x, v.y, v.z, v.w};
        split4_bf16(vv, g_Wdh, g_Wdl, i);
    } else {
        size_t i = (gid - PREP_N0 - PREP_N1 - PREP_N2 - PREP_N3) * 4;
        *(float4*)(g_xp + i) = make_float4(0.f, 0.f, 0.f, 0.f);
    }
}

// xp cols [0,256) -> bf16 hi/lo (delta_raw operand; runs after G1)
__global__ void __launch_bounds__(256)
split_xp_k() {
    size_t i = ((size_t)blockIdx.x * blockDim.x + threadIdx.x) * 4;   // over 1024*256
    int row = (int)(i >> 8);
    int col = (int)(i & 255);
    float4 v = *(const float4*)(g_xp + (size_t)row * XP_COLS + col);
    float vv[4] = {v.x, v.y, v.z, v.w};
    split4_bf16(vv, g_dh, g_dl, i);
}

// ---------------------------------------------------------------------------
// Unified HMMA GEMM: C[m,n] (+)= sum_k A[m,k]*B[n,k], 16-bit operands.
//   ASPLIT: A = Ah + Al. BSPLIT: adds Ah*Bl cross term.
// CTA 128x128, BK=32, 8 warps (2Mx4N), warp tile 64x32. 80B-padded SMEM rows.
// EPI: 0 = plain store, 2 = guarded atomicAdd (split-K),
//      3 = FUSED MAMBA STATE UPDATE:
//          delta = softplus(acc + bias[d]);
//          h_new[b,d,:] = exp(delta*A)*h[b,d,:] + delta*B[b,:]*x[b,d]
//          g_Yh[b,d]    = fp16( C[b,:].h_new + D[d]*x[b,d] )
// ---------------------------------------------------------------------------
#define ROW_B 80
#define TILE_B (128 * ROW_B)          // 10240

template<int DT, bool ASPLIT, bool BSPLIT, int EPI, int NSTAGE>
__global__ void __launch_bounds__(256, 1)
gemm16(const uint16_t* __restrict__ Ah, const uint16_t* __restrict__ Al,
       const uint16_t* __restrict__ Bh, const uint16_t* __restrict__ Bl,
       float* __restrict__ C, int ldc, int ldab, int niters,
       const float* __restrict__ bias, int n_real,
       const float* __restrict__ xg, const float* __restrict__ hg,
       float* __restrict__ hng, const float* __restrict__ Alog,
       const float* __restrict__ Dvg)
{
    constexpr int NTILES = 1 + (ASPLIT ? 1 : 0) + 1 + (BSPLIT ? 1 : 0);
    constexpr uint32_t OFF_A0 = 0;
    constexpr uint32_t OFF_A1 = ASPLIT ? TILE_B : 0;
    constexpr uint32_t OFF_B0 = (ASPLIT ? 2 : 1) * TILE_B;
    constexpr uint32_t OFF_B1 = (ASPLIT ? 3 : 2) * TILE_B;   // only if BSPLIT
    constexpr uint32_t STAGE = NTILES * TILE_B;

    extern __shared__ char smem[];
    __shared__ float sSA[D_STATE];
    const uint32_t sb = smem_u32(smem);
    const int tid = threadIdx.x;
    const int wid = tid >> 5;
    const int lane = tid & 31;
    const int warp_m = wid >> 2;
    const int warp_n = wid & 3;
    const int bm = blockIdx.x * 128;
    const int bn = blockIdx.y * 128;
    const int k_begin = blockIdx.z * niters * 32;

    if constexpr (EPI == 3) {
        if (tid < D_STATE) sSA[tid] = -expf(Alog[tid]);
    }

    auto load_stage = [&](uint32_t st, int k0) {
        #pragma unroll
        for (int cc = 0; cc < 2; cc++) {
            const int idx = tid + 256 * cc;
            const int row = idx >> 2;
            const int ch  = idx & 3;
            const uint32_t d = st + (uint32_t)(row * ROW_B + ch * 16);
            const int gk = k0 + ch * 8;
            cpasync16(d + OFF_A0, Ah + (size_t)(bm + row) * ldab + gk);
            if constexpr (ASPLIT)
                cpasync16(d + OFF_A1, Al + (size_t)(bm + row) * ldab + gk);
            cpasync16(d + OFF_B0, Bh + (size_t)(bn + row) * ldab + gk);
            if constexpr (BSPLIT)
                cpasync16(d + OFF_B1, Bl + (size_t)(bn + row) * ldab + gk);
        }
        cpasync_commit();
    };

    // ldmatrix per-lane byte offsets (within a tile, ks=0)
    uint32_t aoff[4], boff[2];
    #pragma unroll
    for (int mi = 0; mi < 4; mi++)
        aoff[mi] = (uint32_t)((warp_m * 64 + mi * 16 + (lane & 15)) * ROW_B + (lane >> 4) * 16);
    #pragma unroll
    for (int pi = 0; pi < 2; pi++) {
        int chunk = lane >> 3;
        int n = warp_n * 32 + pi * 16 + (chunk >> 1) * 8 + (lane & 7);
        boff[pi] = (uint32_t)(n * ROW_B + (chunk & 1) * 16);
    }

    float acc[4][4][4];
    #pragma unroll
    for (int mi = 0; mi < 4; mi++)
        #pragma unroll
        for (int ni = 0; ni < 4; ni++)
            #pragma unroll
            for (int q = 0; q < 4; q++) acc[mi][ni][q] = 0.0f;

    // prologue: stages 0..NSTAGE-2
    #pragma unroll
    for (int s = 0; s < NSTAGE - 1; s++)
        load_stage(sb + s * STAGE, k_begin + s * 32);

    for (int it = 0; it < niters; it++) {
        if (it + NSTAGE - 1 < niters)
            load_stage(sb + ((it + NSTAGE - 1) % NSTAGE) * STAGE,
                       k_begin + (it + NSTAGE - 1) * 32);
        else
            cpasync_commit();   // keep group count uniform
        asm volatile("cp.async.wait_group %0;" :: "n"(NSTAGE - 1) : "memory");
        __syncthreads();

        const uint32_t st = sb + (it % NSTAGE) * STAGE;
        #pragma unroll
        for (int ks = 0; ks < 2; ks++) {
            uint32_t a0[4][4], a1[4][4], b0[2][4], b1[2][4];
            #pragma unroll
            for (int mi = 0; mi < 4; mi++) {
                ldmatrix_x4(a0[mi], st + OFF_A0 + aoff[mi] + ks * 32);
                if constexpr (ASPLIT)
                    ldmatrix_x4(a1[mi], st + OFF_A1 + aoff[mi] + ks * 32);
            }
            #pragma unroll
            for (int pi = 0; pi < 2; pi++) {
                ldmatrix_x4(b0[pi], st + OFF_B0 + boff[pi] + ks * 32);
                if constexpr (BSPLIT)
                    ldmatrix_x4(b1[pi], st + OFF_B1 + boff[pi] + ks * 32);
            }
            #pragma unroll
            for (int mi = 0; mi < 4; mi++) {
                #pragma unroll
                for (int ni = 0; ni < 4; ni++) {
                    const int pi = ni >> 1;
                    const int sel = (ni & 1) * 2;
                    uint32_t bh[2] = {b0[pi][sel], b0[pi][sel + 1]};
                    mma16<DT>(acc[mi][ni], a0[mi], bh);
                    if constexpr (ASPLIT)
                        mma16<DT>(acc[mi][ni], a1[mi], bh);
                    if constexpr (BSPLIT) {
                        uint32_t bl[2] = {b1[pi][sel], b1[pi][sel + 1]};
                        mma16<DT>(acc[mi][ni], a0[mi], bl);
                    }
                }
            }
        }
        __syncthreads();
    }

    // ---------------- epilogue ----------------
    if constexpr (EPI == 3) {
        // fused selective-state update; C unused
        #pragma unroll
        for (int mi = 0; mi < 4; mi++) {
            #pragma unroll
            for (int rh = 0; rh < 2; rh++) {
                const int b = bm + warp_m * 64 + mi * 16 + rh * 8 + (lane >> 2);
                // B, C vectors for row b (L1/L2-hot; g_xp is 1.2 MB)
                float Bv[D_STATE], Cv[D_STATE];
                const float4* bc = (const float4*)(g_xp + (size_t)b * XP_COLS + DT_RANK);
                #pragma unroll
                for (int t = 0; t < 4; t++) {
                    float4 v = bc[t];
                    Bv[4 * t] = v.x; Bv[4 * t + 1] = v.y; Bv[4 * t + 2] = v.z; Bv[4 * t + 3] = v.w;
                }
                #pragma unroll
                for (int t = 0; t < 4; t++) {
                    float4 v = bc[4 + t];
                    Cv[4 * t] = v.x; Cv[4 * t + 1] = v.y; Cv[4 * t + 2] = v.z; Cv[4 * t + 3] = v.w;
                }
                #pragma unroll
                for (int ni = 0; ni < 4; ni++) {
                    #pragma unroll
                    for (int q2 = 0; q2 < 2; q2++) {
                        const int d = bn + warp_n * 32 + ni * 8 + (lane & 3) * 2 + q2;
                        const float delta = softplusf(acc[mi][ni][rh * 2 + q2] + bias[d]);
                        const size_t bd = (size_t)b * D_MODEL + d;
                        const float xv = xg[bd];
                        const float dxv = delta * xv;
                        const float4* hp = (const float4*)(hg + bd * D_STATE);
                        float4* hop = (float4*)(hng + bd * D_STATE);
                        float accy = 0.0f;
                        #pragma unroll
                        for (int t = 0; t < 4; t++) {
                            float4 hv = __ldcs(hp + t);
                            float h0 = __expf(delta * sSA[4 * t + 0]) * hv.x + dxv * Bv[4 * t + 0];
                            float h1 = __expf(delta * sSA[4 * t + 1]) * hv.y + dxv * Bv[4 * t + 1];
                            float h2 = __expf(delta * sSA[4 * t + 2]) * hv.z + dxv * Bv[4 * t + 2];
                            float h3 = __expf(delta * sSA[4 * t + 3]) * hv.w + dxv * Bv[4 * t + 3];
                            accy += Cv[4 * t + 0] * h0 + Cv[4 * t + 1] * h1
                                  + Cv[4 * t + 2] * h2 + Cv[4 * t + 3] * h3;
                            __stcs(hop + t, make_float4(h0, h1, h2, h3));
                        }
                        float ypre = accy + Dvg[d] * xv;
                        __half hh = __float2half_rn(ypre);
                        g_Yh[bd] = *(uint16_t*)&hh;
                    }
                }
            }
        }
    } else {
        #pragma unroll
        for (int mi = 0; mi < 4; mi++) {
            const int row = bm + warp_m * 64 + mi * 16 + (lane >> 2);
            #pragma unroll
            for (int ni = 0; ni < 4; ni++) {
                const int col = bn + warp_n * 32 + ni * 8 + (lane & 3) * 2;
                float* acc4 = acc[mi][ni];
                if constexpr (EPI == 0) {
                    __stcs((float2*)(C + (size_t)row * ldc + col), make_float2(acc4[0], acc4[1]));
                    __stcs((float2*)(C + (size_t)(row + 8) * ldc + col), make_float2(acc4[2], acc4[3]));
                } else {
                    if (col < n_real) {   // col even, n_real even -> covers col+1
                        atomicAdd(&C[(size_t)row * ldc + col],       acc4[0]);
                        atomicAdd(&C[(size_t)row * ldc + col + 1],   acc4[1]);
                        atomicAdd(&C[(size_t)(row + 8) * ldc + col],     acc4[2]);
                        atomicAdd(&C[(size_t)(row + 8) * ldc + col + 1], acc4[3]);
                    }
                }
            }
        }
    }
}

// ---------------------------------------------------------------------------
// Launch. Inputs: x, h, W_xproj, W_dt, b_dt, A_log, D, W_out.
// Output: [y (1024*4096), h_new (1024*4096*16)].
// ---------------------------------------------------------------------------
extern "C" void kernel_launch(void* const* d_in, const int* in_sizes, int n_in,
                              void* d_out, int out_size)
{
    const float* x    = (const float*)d_in[0];
    const float* h    = (const float*)d_in[1];
    const float* Wxp  = (const float*)d_in[2];
    const float* Wdt  = (const float*)d_in[3];
    const float* bdt  = (const float*)d_in[4];
    const float* Alog = (const float*)d_in[5];
    const float* Dv   = (const float*)d_in[6];
    const float* Wout = (const float*)d_in[7];

    float* y_out    = (float*)d_out;
    float* hnew_out = y_out + (size_t)BATCH * D_MODEL;

    float *xp_p;
    uint16_t *Wh16_p, *Yh_p, *xh_p, *xl_p, *Wxh_p, *Wxl_p, *dh_p, *dl_p, *Wdh_p, *Wdl_p;
    cudaGetSymbolAddress((void**)&xp_p, g_xp);
    cudaGetSymbolAddress((void**)&Wh16_p, g_Wh16);
    cudaGetSymbolAddress((void**)&Yh_p, g_Yh);
    cudaGetSymbolAddress((void**)&xh_p, g_xh);
    cudaGetSymbolAddress((void**)&xl_p, g_xl);
    cudaGetSymbolAddress((void**)&Wxh_p, g_Wxh);
    cudaGetSymbolAddress((void**)&Wxl_p, g_Wxl);
    cudaGetSymbolAddress((void**)&dh_p, g_dh);
    cudaGetSymbolAddress((void**)&dl_p, g_dl);
    cudaGetSymbolAddress((void**)&Wdh_p, g_Wdh);
    cudaGetSymbolAddress((void**)&Wdl_p, g_Wdl);

    const int SMEM4 = 2 * 4 * TILE_B;   // 81920  (bf16x3: 4 tiles, 2 stages)
    const int SMEM2 = 4 * 2 * TILE_B;   // 81920  (fp16x1: 2 tiles, 4 stages)
    cudaFuncSetAttribute((const void*)gemm16<0, true, true, 2, 2>,
                         cudaFuncAttributeMaxDynamicSharedMemorySize, SMEM4);
    cudaFuncSetAttribute((const void*)gemm16<0, true, true, 3, 2>,
                         cudaFuncAttributeMaxDynamicSharedMemorySize, SMEM4);
    cudaFuncSetAttribute((const void*)gemm16<1, false, false, 0, 4>,
                         cudaFuncAttributeMaxDynamicSharedMemorySize, SMEM2);

    // 1) All operand preparation in one launch (incl. zeroing g_xp)
    prep_all<<<(unsigned)(PREP_TOT / 256), 256>>>(Wout, x, Wxp, Wdt);

    // 2) G1: xp = x @ W_xproj^T  (bf16x3 HMMA, split-K=8, guarded atomic epilogue)
    gemm16<0, true, true, 2, 2><<<dim3(BATCH / 128, WXP_PAD / 128, 8), 256, SMEM4>>>(
        xh_p, xl_p, Wxh_p, Wxl_p, xp_p, XP_COLS, D_MODEL, (D_MODEL / 8) / 32,
        nullptr, XP_COLS, nullptr, nullptr, nullptr, nullptr, nullptr);

    // 3) delta_raw split (xp cols 0..255 -> bf16 hi/lo)
    split_xp_k<<<(BATCH * DT_RANK) / (4 * 256), 256>>>();

    // 4) G2 + fused state update: delta GEMM epilogue does the h update,
    //    writes h_new (fp32 output) and ypre -> fp16 g_Yh
    gemm16<0, true, true, 3, 2><<<dim3(BATCH / 128, D_MODEL / 128, 1), 256, SMEM4>>>(
        dh_p, dl_p, Wdh_p, Wdl_p, nullptr, D_MODEL, DT_RANK, DT_RANK / 32,
        bdt, D_MODEL, x, h, hnew_out, Alog, Dv);

    // 5) G3: y = fp16(ypre) @ fp16(W_out)^T  (single product, 4-stage pipeline)
    gemm16<1, false, false, 0, 4><<<dim3(BATCH / 128, D_MODEL / 128, 1), 256, SMEM2>>>(
        Yh_p, nullptr, Wh16_p, nullptr, y_out, D_MODEL, D_MODEL, D_MODEL / 32,
        nullptr, D_MODEL, nullptr, nullptr, nullptr, nullptr, nullptr);
}

// round 8
// speedup vs baseline: 1.1729x; 1.1729x over previous
#include <cuda_runtime.h>
#include <cuda_bf16.h>
#include <cuda_fp16.h>
#include <math.h>
#include <stdint.h>

#define BATCH   1024
#define D_MODEL 4096
#define D_STATE 16
#define DT_RANK 256
#define XP_COLS (DT_RANK + 2 * D_STATE)   // 288
#define WXP_PAD 384                        // 288 padded to 3 x 128

// ---------------- scratch (allocation-free rule: __device__ globals) --------
__device__ float g_xp[BATCH * XP_COLS];
__device__ float g_delta[BATCH * D_MODEL];
__device__ uint16_t g_Wh16[(size_t)D_MODEL * D_MODEL];   // fp16(W_out)
__device__ uint16_t g_Yh[(size_t)BATCH * D_MODEL];       // fp16(ypre)
__device__ uint16_t g_xh[(size_t)BATCH * D_MODEL];       // bf16 hi(x)
__device__ uint16_t g_xl[(size_t)BATCH * D_MODEL];       // bf16 lo(x)
__device__ uint16_t g_Wxh[(size_t)WXP_PAD * D_MODEL];    // bf16 hi(W_xproj), padded
__device__ uint16_t g_Wxl[(size_t)WXP_PAD * D_MODEL];
__device__ uint16_t g_dh[(size_t)BATCH * DT_RANK];       // bf16 hi(delta_raw)
__device__ uint16_t g_dl[(size_t)BATCH * DT_RANK];
__device__ uint16_t g_Wdh[(size_t)D_MODEL * DT_RANK];    // bf16 hi(W_dt)
__device__ uint16_t g_Wdl[(size_t)D_MODEL * DT_RANK];

__device__ __forceinline__ float softplusf(float z) {
    return (z > 20.0f) ? z : log1pf(__expf(z));
}

// ---------------- PTX helpers (sm_80-class only; no 'a'-target features) ----
__device__ __forceinline__ uint32_t smem_u32(const void* p) {
    uint32_t a;
    asm("{ .reg .u64 t; cvta.to.shared.u64 t, %1; cvt.u32.u64 %0, t; }" : "=r"(a) : "l"(p));
    return a;
}
__device__ __forceinline__ void cpasync16(uint32_t dst, const void* src) {
    asm volatile("cp.async.cg.shared.global [%0], [%1], 16;" :: "r"(dst), "l"(src));
}
__device__ __forceinline__ void cpasync_commit() {
    asm volatile("cp.async.commit_group;" ::: "memory");
}
__device__ __forceinline__ void ldmatrix_x4(uint32_t* r, uint32_t addr) {
    asm volatile("ldmatrix.sync.aligned.m8n8.x4.shared.b16 {%0,%1,%2,%3}, [%4];"
                 : "=r"(r[0]), "=r"(r[1]), "=r"(r[2]), "=r"(r[3]) : "r"(addr));
}
// DT: 0 = bf16, 1 = fp16
template<int DT>
__device__ __forceinline__ void mma16(float* c, const uint32_t* a, const uint32_t* b) {
    if constexpr (DT == 0) {
        asm volatile(
            "mma.sync.aligned.m16n8k16.row.col.f32.bf16.bf16.f32 "
            "{%0,%1,%2,%3}, {%4,%5,%6,%7}, {%8,%9}, {%0,%1,%2,%3};"
            : "+f"(c[0]), "+f"(c[1]), "+f"(c[2]), "+f"(c[3])
            : "r"(a[0]), "r"(a[1]), "r"(a[2]), "r"(a[3]), "r"(b[0]), "r"(b[1]));
    } else {
        asm volatile(
            "mma.sync.aligned.m16n8k16.row.col.f32.f16.f16.f32 "
            "{%0,%1,%2,%3}, {%4,%5,%6,%7}, {%8,%9}, {%0,%1,%2,%3};"
            : "+f"(c[0]), "+f"(c[1]), "+f"(c[2]), "+f"(c[3])
            : "r"(a[0]), "r"(a[1]), "r"(a[2]), "r"(a[3]), "r"(b[0]), "r"(b[1]));
    }
}

// ---------------------------------------------------------------------------
// Merged preparation kernel (single launch):
//   W_out -> fp16; x -> bf16 hi/lo; W_xproj -> bf16 hi/lo padded;
//   W_dt -> bf16 hi/lo; zero g_xp.
// ---------------------------------------------------------------------------
#define PREP_N0 ((size_t)D_MODEL * D_MODEL / 4)
#define PREP_N1 ((size_t)BATCH * D_MODEL / 4)
#define PREP_N2 ((size_t)WXP_PAD * D_MODEL / 4)
#define PREP_N3 ((size_t)D_MODEL * DT_RANK / 4)
#define PREP_N4 ((size_t)BATCH * XP_COLS / 4)
#define PREP_TOT (PREP_N0 + PREP_N1 + PREP_N2 + PREP_N3 + PREP_N4)

__device__ __forceinline__ void split4_bf16(const float* vv, uint16_t* h, uint16_t* l, size_t i) {
    #pragma unroll
    for (int q = 0; q < 4; q++) {
        __nv_bfloat16 hi = __float2bfloat16(vv[q]);
        __nv_bfloat16 lo = __float2bfloat16(vv[q] - __bfloat162float(hi));
        h[i + q] = *(uint16_t*)&hi;
        l[i + q] = *(uint16_t*)&lo;
    }
}

__global__ void __launch_bounds__(256)
prep_all(const float* __restrict__ Wout, const float* __restrict__ x,
         const float* __restrict__ Wxp, const float* __restrict__ Wdt)
{
    size_t gid = (size_t)blockIdx.x * 256 + threadIdx.x;
    if (gid < PREP_N0) {
        size_t i = gid * 4;
        float4 v = *(const float4*)(Wout + i);
        __half h0 = __float2half_rn(v.x), h1 = __float2half_rn(v.y);
        __half h2 = __float2half_rn(v.z), h3 = __float2half_rn(v.w);
        uint16_t* o = g_Wh16 + i;
        o[0] = *(uint16_t*)&h0; o[1] = *(uint16_t*)&h1;
        o[2] = *(uint16_t*)&h2; o[3] = *(uint16_t*)&h3;
    } else if (gid < PREP_N0 + PREP_N1) {
        size_t i = (gid - PREP_N0) * 4;
        float4 v = *(const float4*)(x + i);
        float vv[4] = {v.x, v.y, v.z, v.w};
        split4_bf16(vv, g_xh, g_xl, i);
    } else if (gid < PREP_N0 + PREP_N1 + PREP_N2) {
        size_t i = (gid - PREP_N0 - PREP_N1) * 4;
        int row = (int)(i >> 12);
        float vv[4] = {0.f, 0.f, 0.f, 0.f};
        if (row < XP_COLS) {
            float4 v = *(const float4*)(Wxp + i);
            vv[0] = v.x; vv[1] = v.y; vv[2] = v.z; vv[3] = v.w;
        }
        split4_bf16(vv, g_Wxh, g_Wxl, i);
    } else if (gid < PREP_N0 + PREP_N1 + PREP_N2 + PREP_N3) {
        size_t i = (gid - PREP_N0 - PREP_N1 - PREP_N2) * 4;
        float4 v = *(const float4*)(Wdt + i);
        float vv[4] = {v.x, v.y, v.z, v.w};
        split4_bf16(vv, g_Wdh, g_Wdl, i);
    } else {
        size_t i = (gid - PREP_N0 - PREP_N1 - PREP_N2 - PREP_N3) * 4;
        *(float4*)(g_xp + i) = make_float4(0.f, 0.f, 0.f, 0.f);
    }
}

// xp cols [0,256) -> bf16 hi/lo (delta_raw operand; runs after G1)
__global__ void __launch_bounds__(256)
split_xp_k() {
    size_t i = ((size_t)blockIdx.x * blockDim.x + threadIdx.x) * 4;   // over 1024*256
    int row = (int)(i >> 8);
    int col = (int)(i & 255);
    float4 v = *(const float4*)(g_xp + (size_t)row * XP_COLS + col);
    float vv[4] = {v.x, v.y, v.z, v.w};
    split4_bf16(vv, g_dh, g_dl, i);
}

// ---------------------------------------------------------------------------
// Standalone fused state update (16384 CTAs -> full memory parallelism).
// Streaming hints: h/h_new are single-touch (512 MB), keep them out of L2.
// ---------------------------------------------------------------------------
__global__ void __launch_bounds__(256)
state_update(const float* __restrict__ x,
             const float* __restrict__ h,
             const float* __restrict__ A_log,
             const float* __restrict__ Dv,
             float* __restrict__ h_new)
{
    __shared__ float sA[D_STATE], sB[D_STATE], sC[D_STATE];
    const int b = blockIdx.y;
    const int d = blockIdx.x * blockDim.x + threadIdx.x;

    if (threadIdx.x < D_STATE) {
        int n = threadIdx.x;
        sA[n] = -expf(A_log[n]);
        sB[n] = g_xp[(size_t)b * XP_COLS + DT_RANK + n];
        sC[n] = g_xp[(size_t)b * XP_COLS + DT_RANK + D_STATE + n];
    }
    __syncthreads();

    const size_t bd = (size_t)b * D_MODEL + d;
    const float delta = g_delta[bd];
    const float xv = x[bd];
    const float dx = delta * xv;

    const float4* hp = (const float4*)(h + bd * D_STATE);
    float4* hop = (float4*)(h_new + bd * D_STATE);

    float acc = 0.0f;
    #pragma unroll
    for (int q = 0; q < 4; q++) {
        float4 hv = __ldcs(hp + q);
        float h0 = __expf(delta * sA[4 * q + 0]) * hv.x + dx * sB[4 * q + 0];
        float h1 = __expf(delta * sA[4 * q + 1]) * hv.y + dx * sB[4 * q + 1];
        float h2 = __expf(delta * sA[4 * q + 2]) * hv.z + dx * sB[4 * q + 2];
        float h3 = __expf(delta * sA[4 * q + 3]) * hv.w + dx * sB[4 * q + 3];
        acc += sC[4 * q + 0] * h0 + sC[4 * q + 1] * h1
             + sC[4 * q + 2] * h2 + sC[4 * q + 3] * h3;
        __stcs(hop + q, make_float4(h0, h1, h2, h3));
    }
    float ypre = acc + Dv[d] * xv;
    __half hi = __float2half_rn(ypre);
    g_Yh[bd] = *(uint16_t*)&hi;
}

// ---------------------------------------------------------------------------
// Unified HMMA GEMM: C[m,n] (+)= sum_k A[m,k]*B[n,k], 16-bit operands.
//   ASPLIT: A = Ah + Al. BSPLIT: adds Ah*Bl cross term.
// CTA 128x128, BK=32, 8 warps (2Mx4N), warp tile 64x32. 80B-padded SMEM rows.
// EPI: 0 = plain store, 1 = softplus(acc+bias[col]) store, 2 = guarded atomicAdd.
// Split-K via blockIdx.z.
// ---------------------------------------------------------------------------
#define ROW_B 80
#define TILE_B (128 * ROW_B)          // 10240

template<int DT, bool ASPLIT, bool BSPLIT, int EPI, int NSTAGE>
__global__ void __launch_bounds__(256, 1)
gemm16(const uint16_t* __restrict__ Ah, const uint16_t* __restrict__ Al,
       const uint16_t* __restrict__ Bh, const uint16_t* __restrict__ Bl,
       float* __restrict__ C, int ldc, int ldab, int niters,
       const float* __restrict__ bias, int n_real)
{
    constexpr int NTILES = 1 + (ASPLIT ? 1 : 0) + 1 + (BSPLIT ? 1 : 0);
    constexpr uint32_t OFF_A0 = 0;
    constexpr uint32_t OFF_A1 = ASPLIT ? TILE_B : 0;
    constexpr uint32_t OFF_B0 = (ASPLIT ? 2 : 1) * TILE_B;
    constexpr uint32_t OFF_B1 = (ASPLIT ? 3 : 2) * TILE_B;   // only if BSPLIT
    constexpr uint32_t STAGE = NTILES * TILE_B;

    extern __shared__ char smem[];
    const uint32_t sb = smem_u32(smem);
    const int tid = threadIdx.x;
    const int wid = tid >> 5;
    const int lane = tid & 31;
    const int warp_m = wid >> 2;
    const int warp_n = wid & 3;
    const int bm = blockIdx.x * 128;
    const int bn = blockIdx.y * 128;
    const int k_begin = blockIdx.z * niters * 32;

    auto load_stage = [&](uint32_t st, int k0) {
        #pragma unroll
        for (int cc = 0; cc < 2; cc++) {
            const int idx = tid + 256 * cc;
            const int row = idx >> 2;
            const int ch  = idx & 3;
            const uint32_t d = st + (uint32_t)(row * ROW_B + ch * 16);
            const int gk = k0 + ch * 8;
            cpasync16(d + OFF_A0, Ah + (size_t)(bm + row) * ldab + gk);
            if constexpr (ASPLIT)
                cpasync16(d + OFF_A1, Al + (size_t)(bm + row) * ldab + gk);
            cpasync16(d + OFF_B0, Bh + (size_t)(bn + row) * ldab + gk);
            if constexpr (BSPLIT)
                cpasync16(d + OFF_B1, Bl + (size_t)(bn + row) * ldab + gk);
        }
        cpasync_commit();
    };

    // ldmatrix per-lane byte offsets (within a tile, ks=0)
    uint32_t aoff[4], boff[2];
    #pragma unroll
    for (int mi = 0; mi < 4; mi++)
        aoff[mi] = (uint32_t)((warp_m * 64 + mi * 16 + (lane & 15)) * ROW_B + (lane >> 4) * 16);
    #pragma unroll
    for (int pi = 0; pi < 2; pi++) {
        int chunk = lane >> 3;
        int n = warp_n * 32 + pi * 16 + (chunk >> 1) * 8 + (lane & 7);
        boff[pi] = (uint32_t)(n * ROW_B + (chunk & 1) * 16);
    }

    float acc[4][4][4];
    #pragma unroll
    for (int mi = 0; mi < 4; mi++)
        #pragma unroll
        for (int ni = 0; ni < 4; ni++)
            #pragma unroll
            for (int q = 0; q < 4; q++) acc[mi][ni][q] = 0.0f;

    // prologue: stages 0..NSTAGE-2
    #pragma unroll
    for (int s = 0; s < NSTAGE - 1; s++)
        load_stage(sb + s * STAGE, k_begin + s * 32);

    for (int it = 0; it < niters; it++) {
        if (it + NSTAGE - 1 < niters)
            load_stage(sb + ((it + NSTAGE - 1) % NSTAGE) * STAGE,
                       k_begin + (it + NSTAGE - 1) * 32);
        else
            cpasync_commit();   // keep group count uniform
        asm volatile("cp.async.wait_group %0;" :: "n"(NSTAGE - 1) : "memory");
        __syncthreads();

        const uint32_t st = sb + (it % NSTAGE) * STAGE;
        #pragma unroll
        for (int ks = 0; ks < 2; ks++) {
            uint32_t a0[4][4], a1[4][4], b0[2][4], b1[2][4];
            #pragma unroll
            for (int mi = 0; mi < 4; mi++) {
                ldmatrix_x4(a0[mi], st + OFF_A0 + aoff[mi] + ks * 32);
                if constexpr (ASPLIT)
                    ldmatrix_x4(a1[mi], st + OFF_A1 + aoff[mi] + ks * 32);
            }
            #pragma unroll
            for (int pi = 0; pi < 2; pi++) {
                ldmatrix_x4(b0[pi], st + OFF_B0 + boff[pi] + ks * 32);
                if constexpr (BSPLIT)
                    ldmatrix_x4(b1[pi], st + OFF_B1 + boff[pi] + ks * 32);
            }
            #pragma unroll
            for (int mi = 0; mi < 4; mi++) {
                #pragma unroll
                for (int ni = 0; ni < 4; ni++) {
                    const int pi = ni >> 1;
                    const int sel = (ni & 1) * 2;
                    uint32_t bh[2] = {b0[pi][sel], b0[pi][sel + 1]};
                    mma16<DT>(acc[mi][ni], a0[mi], bh);
                    if constexpr (ASPLIT)
                        mma16<DT>(acc[mi][ni], a1[mi], bh);
                    if constexpr (BSPLIT) {
                        uint32_t bl[2] = {b1[pi][sel], b1[pi][sel + 1]};
                        mma16<DT>(acc[mi][ni], a0[mi], bl);
                    }
                }
            }
        }
        __syncthreads();
    }

    // epilogue
    #pragma unroll
    for (int mi = 0; mi < 4; mi++) {
        const int row = bm + warp_m * 64 + mi * 16 + (lane >> 2);
        #pragma unroll
        for (int ni = 0; ni < 4; ni++) {
            const int col = bn + warp_n * 32 + ni * 8 + (lane & 3) * 2;
            float* acc4 = acc[mi][ni];
            if constexpr (EPI == 0) {
                __stcs((float2*)(C + (size_t)row * ldc + col), make_float2(acc4[0], acc4[1]));
                __stcs((float2*)(C + (size_t)(row + 8) * ldc + col), make_float2(acc4[2], acc4[3]));
            } else if constexpr (EPI == 1) {
                float b0v = bias[col], b1v = bias[col + 1];
                *(float2*)(C + (size_t)row * ldc + col) =
                    make_float2(softplusf(acc4[0] + b0v), softplusf(acc4[1] + b1v));
                *(float2*)(C + (size_t)(row + 8) * ldc + col) =
                    make_float2(softplusf(acc4[2] + b0v), softplusf(acc4[3] + b1v));
            } else {
                if (col < n_real) {   // col even, n_real even -> covers col+1
                    atomicAdd(&C[(size_t)row * ldc + col],       acc4[0]);
                    atomicAdd(&C[(size_t)row * ldc + col + 1],   acc4[1]);
                    atomicAdd(&C[(size_t)(row + 8) * ldc + col],     acc4[2]);
                    atomicAdd(&C[(size_t)(row + 8) * ldc + col + 1], acc4[3]);
                }
            }
        }
    }
}

// ---------------------------------------------------------------------------
// Launch. Inputs: x, h, W_xproj, W_dt, b_dt, A_log, D, W_out.
// Output: [y (1024*4096), h_new (1024*4096*16)].
// ---------------------------------------------------------------------------
extern "C" void kernel_launch(void* const* d_in, const int* in_sizes, int n_in,
                              void* d_out, int out_size)
{
    const float* x    = (const float*)d_in[0];
    const float* h    = (const float*)d_in[1];
    const float* Wxp  = (const float*)d_in[2];
    const float* Wdt  = (const float*)d_in[3];
    const float* bdt  = (const float*)d_in[4];
    const float* Alog = (const float*)d_in[5];
    const float* Dv   = (const float*)d_in[6];
    const float* Wout = (const float*)d_in[7];

    float* y_out    = (float*)d_out;
    float* hnew_out = y_out + (size_t)BATCH * D_MODEL;

    float *xp_p, *delta_p;
    uint16_t *Wh16_p, *Yh_p, *xh_p, *xl_p, *Wxh_p, *Wxl_p, *dh_p, *dl_p, *Wdh_p, *Wdl_p;
    cudaGetSymbolAddress((void**)&xp_p, g_xp);
    cudaGetSymbolAddress((void**)&delta_p, g_delta);
    cudaGetSymbolAddress((void**)&Wh16_p, g_Wh16);
    cudaGetSymbolAddress((void**)&Yh_p, g_Yh);
    cudaGetSymbolAddress((void**)&xh_p, g_xh);
    cudaGetSymbolAddress((void**)&xl_p, g_xl);
    cudaGetSymbolAddress((void**)&Wxh_p, g_Wxh);
    cudaGetSymbolAddress((void**)&Wxl_p, g_Wxl);
    cudaGetSymbolAddress((void**)&dh_p, g_dh);
    cudaGetSymbolAddress((void**)&dl_p, g_dl);
    cudaGetSymbolAddress((void**)&Wdh_p, g_Wdh);
    cudaGetSymbolAddress((void**)&Wdl_p, g_Wdl);

    const int SMEM4 = 2 * 4 * TILE_B;   // 81920  (bf16x3: 4 tiles, 2 stages)
    const int SMEM2 = 4 * 2 * TILE_B;   // 81920  (fp16x1: 2 tiles, 4 stages)
    cudaFuncSetAttribute((const void*)gemm16<0, true, true, 2, 2>,
                         cudaFuncAttributeMaxDynamicSharedMemorySize, SMEM4);
    cudaFuncSetAttribute((const void*)gemm16<0, true, true, 1, 2>,
                         cudaFuncAttributeMaxDynamicSharedMemorySize, SMEM4);
    cudaFuncSetAttribute((const void*)gemm16<1, false, false, 0, 4>,
                         cudaFuncAttributeMaxDynamicSharedMemorySize, SMEM2);

    // 1) All operand preparation in one launch (incl. zeroing g_xp)
    prep_all<<<(unsigned)(PREP_TOT / 256), 256>>>(Wout, x, Wxp, Wdt);

    // 2) G1: xp = x @ W_xproj^T  (bf16x3 HMMA, split-K=8, guarded atomic epilogue)
    gemm16<0, true, true, 2, 2><<<dim3(BATCH / 128, WXP_PAD / 128, 8), 256, SMEM4>>>(
        xh_p, xl_p, Wxh_p, Wxl_p, xp_p, XP_COLS, D_MODEL, (D_MODEL / 8) / 32,
        nullptr, XP_COLS);

    // 3) delta_raw split (xp cols 0..255 -> bf16 hi/lo)
    split_xp_k<<<(BATCH * DT_RANK) / (4 * 256), 256>>>();

    // 4) G2: delta = softplus(delta_raw @ W_dt^T + b_dt)  (bf16x3 HMMA)
    gemm16<0, true, true, 1, 2><<<dim3(BATCH / 128, D_MODEL / 128, 1), 256, SMEM4>>>(
        dh_p, dl_p, Wdh_p, Wdl_p, delta_p, D_MODEL, DT_RANK, DT_RANK / 32,
        bdt, D_MODEL);

    // 5) Standalone state update (full-grid memory parallelism + streaming hints)
    state_update<<<dim3(D_MODEL / 256, BATCH), 256>>>(x, h, Alog, Dv, hnew_out);

    // 6) G3: y = fp16(ypre) @ fp16(W_out)^T  (single product, 4-stage pipeline)
    gemm16<1, false, false, 0, 4><<<dim3(BATCH / 128, D_MODEL / 128, 1), 256, SMEM2>>>(
        Yh_p, nullptr, Wh16_p, nullptr, y_out, D_MODEL, D_MODEL, D_MODEL / 32,
        nullptr, D_MODEL);
}

// round 9
// speedup vs baseline: 1.3245x; 1.1293x over previous
#include <cuda_runtime.h>
#include <cuda_bf16.h>
#include <cuda_fp16.h>
#include <math.h>
#include <stdint.h>

#define BATCH   1024
#define D_MODEL 4096
#define D_STATE 16
#define DT_RANK 256
#define XP_COLS (DT_RANK + 2 * D_STATE)   // 288
#define WXP_PAD 384                        // 288 padded to 3 x 128

// ---------------- scratch (allocation-free rule: __device__ globals) --------
__device__ float g_xp[BATCH * XP_COLS];
__device__ float g_delta[BATCH * D_MODEL];
__device__ uint16_t g_Wh16[(size_t)D_MODEL * D_MODEL];   // fp16(W_out)
__device__ uint16_t g_Yh[(size_t)BATCH * D_MODEL];       // fp16(ypre)
__device__ uint16_t g_xh[(size_t)BATCH * D_MODEL];       // bf16 hi(x)
__device__ uint16_t g_xl[(size_t)BATCH * D_MODEL];       // bf16 lo(x)
__device__ uint16_t g_Wxh[(size_t)WXP_PAD * D_MODEL];    // bf16 hi(W_xproj), padded
__device__ uint16_t g_Wxl[(size_t)WXP_PAD * D_MODEL];
__device__ uint16_t g_dh[(size_t)BATCH * DT_RANK];       // bf16 hi(delta_raw)
__device__ uint16_t g_dl[(size_t)BATCH * DT_RANK];
__device__ uint16_t g_Wdh[(size_t)D_MODEL * DT_RANK];    // bf16 hi(W_dt)
__device__ uint16_t g_Wdl[(size_t)D_MODEL * DT_RANK];

__device__ __forceinline__ float softplusf(float z) {
    return (z > 20.0f) ? z : log1pf(__expf(z));
}

// ---------------- PTX helpers (sm_80-class only; no 'a'-target features) ----
__device__ __forceinline__ uint32_t smem_u32(const void* p) {
    uint32_t a;
    asm("{ .reg .u64 t; cvta.to.shared.u64 t, %1; cvt.u32.u64 %0, t; }" : "=r"(a) : "l"(p));
    return a;
}
__device__ __forceinline__ void cpasync16(uint32_t dst, const void* src) {
    asm volatile("cp.async.cg.shared.global [%0], [%1], 16;" :: "r"(dst), "l"(src));
}
__device__ __forceinline__ void cpasync_commit() {
    asm volatile("cp.async.commit_group;" ::: "memory");
}
__device__ __forceinline__ void ldmatrix_x4(uint32_t* r, uint32_t addr) {
    asm volatile("ldmatrix.sync.aligned.m8n8.x4.shared.b16 {%0,%1,%2,%3}, [%4];"
                 : "=r"(r[0]), "=r"(r[1]), "=r"(r[2]), "=r"(r[3]) : "r"(addr));
}
// DT: 0 = bf16, 1 = fp16
template<int DT>
__device__ __forceinline__ void mma16(float* c, const uint32_t* a, const uint32_t* b) {
    if constexpr (DT == 0) {
        asm volatile(
            "mma.sync.aligned.m16n8k16.row.col.f32.bf16.bf16.f32 "
            "{%0,%1,%2,%3}, {%4,%5,%6,%7}, {%8,%9}, {%0,%1,%2,%3};"
            : "+f"(c[0]), "+f"(c[1]), "+f"(c[2]), "+f"(c[3])
            : "r"(a[0]), "r"(a[1]), "r"(a[2]), "r"(a[3]), "r"(b[0]), "r"(b[1]));
    } else {
        asm volatile(
            "mma.sync.aligned.m16n8k16.row.col.f32.f16.f16.f32 "
            "{%0,%1,%2,%3}, {%4,%5,%6,%7}, {%8,%9}, {%0,%1,%2,%3};"
            : "+f"(c[0]), "+f"(c[1]), "+f"(c[2]), "+f"(c[3])
            : "r"(a[0]), "r"(a[1]), "r"(a[2]), "r"(a[3]), "r"(b[0]), "r"(b[1]));
    }
}

// ---------------------------------------------------------------------------
// Conversion / split kernels (separate launches — measured-good config)
// ---------------------------------------------------------------------------
__global__ void zero_xp_kernel() {
    int i = blockIdx.x * blockDim.x + threadIdx.x;
    if (i < BATCH * XP_COLS) g_xp[i] = 0.0f;
}

__device__ __forceinline__ void split4_bf16(const float* vv, uint16_t* h, uint16_t* l, size_t i) {
    #pragma unroll
    for (int q = 0; q < 4; q++) {
        __nv_bfloat16 hi = __float2bfloat16(vv[q]);
        __nv_bfloat16 lo = __float2bfloat16(vv[q] - __bfloat162float(hi));
        h[i + q] = *(uint16_t*)&hi;
        l[i + q] = *(uint16_t*)&lo;
    }
}

// fp32 -> bf16 hi/lo
__global__ void __launch_bounds__(256)
split_bf16_k(const float* __restrict__ in, uint16_t* __restrict__ h, uint16_t* __restrict__ l) {
    size_t i = ((size_t)blockIdx.x * blockDim.x + threadIdx.x) * 4;
    float4 v = *(const float4*)(in + i);
    float vv[4] = {v.x, v.y, v.z, v.w};
    split4_bf16(vv, h, l, i);
}

// fp32 -> fp16 single (W_out)
__global__ void __launch_bounds__(256)
conv_fp16_k(const float* __restrict__ in, uint16_t* __restrict__ out) {
    size_t i = ((size_t)blockIdx.x * blockDim.x + threadIdx.x) * 4;
    float4 v = *(const float4*)(in + i);
    __half h0 = __float2half_rn(v.x), h1 = __float2half_rn(v.y);
    __half h2 = __float2half_rn(v.z), h3 = __float2half_rn(v.w);
    uint16_t* o = out + i;
    o[0] = *(uint16_t*)&h0; o[1] = *(uint16_t*)&h1;
    o[2] = *(uint16_t*)&h2; o[3] = *(uint16_t*)&h3;
}

// W_xproj (288x4096) -> bf16 hi/lo padded to 384 rows (zeros beyond 288)
__global__ void __launch_bounds__(256)
split_wxproj_k(const float* __restrict__ in) {
    size_t i = ((size_t)blockIdx.x * blockDim.x + threadIdx.x) * 4;   // over 384*4096
    int row = (int)(i >> 12);
    float vv[4] = {0.f, 0.f, 0.f, 0.f};
    if (row < XP_COLS) {
        float4 v = *(const float4*)(in + i);
        vv[0] = v.x; vv[1] = v.y; vv[2] = v.z; vv[3] = v.w;
    }
    split4_bf16(vv, g_Wxh, g_Wxl, i);
}

// xp cols [0,256) -> bf16 hi/lo (delta_raw operand; runs after G1)
__global__ void __launch_bounds__(256)
split_xp_k() {
    size_t i = ((size_t)blockIdx.x * blockDim.x + threadIdx.x) * 4;   // over 1024*256
    int row = (int)(i >> 8);
    int col = (int)(i & 255);
    float4 v = *(const float4*)(g_xp + (size_t)row * XP_COLS + col);
    float vv[4] = {v.x, v.y, v.z, v.w};
    split4_bf16(vv, g_dh, g_dl, i);
}

// ---------------------------------------------------------------------------
// Standalone fused state update, 2 d-values per thread (MLP 4 -> 8).
// Plain loads/stores (streaming hints reverted — regression suspect).
// ---------------------------------------------------------------------------
__global__ void __launch_bounds__(256)
state_update(const float* __restrict__ x,
             const float* __restrict__ h,
             const float* __restrict__ A_log,
             const float* __restrict__ Dv,
             float* __restrict__ h_new)
{
    __shared__ float sA[D_STATE], sB[D_STATE], sC[D_STATE];
    const int b = blockIdx.y;
    const int d0 = blockIdx.x * 512 + threadIdx.x;

    if (threadIdx.x < D_STATE) {
        int n = threadIdx.x;
        sA[n] = -expf(A_log[n]);
        sB[n] = g_xp[(size_t)b * XP_COLS + DT_RANK + n];
        sC[n] = g_xp[(size_t)b * XP_COLS + DT_RANK + D_STATE + n];
    }
    __syncthreads();

    const size_t bd0 = (size_t)b * D_MODEL + d0;
    const size_t bd1 = bd0 + 256;

    // scalar operands for both d's
    const float delta0 = g_delta[bd0];
    const float delta1 = g_delta[bd1];
    const float xv0 = x[bd0];
    const float xv1 = x[bd1];
    const float Dv0 = Dv[d0];
    const float Dv1 = Dv[d0 + 256];

    // 8 independent 16B loads in flight
    const float4* hp0 = (const float4*)(h + bd0 * D_STATE);
    const float4* hp1 = (const float4*)(h + bd1 * D_STATE);
    float4 hv0[4], hv1[4];
    #pragma unroll
    for (int q = 0; q < 4; q++) hv0[q] = hp0[q];
    #pragma unroll
    for (int q = 0; q < 4; q++) hv1[q] = hp1[q];

    float4* hop0 = (float4*)(h_new + bd0 * D_STATE);
    float4* hop1 = (float4*)(h_new + bd1 * D_STATE);

    const float dx0 = delta0 * xv0;
    const float dx1 = delta1 * xv1;
    float acc0 = 0.0f, acc1 = 0.0f;
    #pragma unroll
    for (int q = 0; q < 4; q++) {
        float a0 = sA[4 * q + 0], a1 = sA[4 * q + 1], a2 = sA[4 * q + 2], a3 = sA[4 * q + 3];
        float B0 = sB[4 * q + 0], B1 = sB[4 * q + 1], B2 = sB[4 * q + 2], B3 = sB[4 * q + 3];
        float C0 = sC[4 * q + 0], C1 = sC[4 * q + 1], C2 = sC[4 * q + 2], C3 = sC[4 * q + 3];

        float u0 = __expf(delta0 * a0) * hv0[q].x + dx0 * B0;
        float u1 = __expf(delta0 * a1) * hv0[q].y + dx0 * B1;
        float u2 = __expf(delta0 * a2) * hv0[q].z + dx0 * B2;
        float u3 = __expf(delta0 * a3) * hv0[q].w + dx0 * B3;
        acc0 += C0 * u0 + C1 * u1 + C2 * u2 + C3 * u3;
        hop0[q] = make_float4(u0, u1, u2, u3);

        float w0 = __expf(delta1 * a0) * hv1[q].x + dx1 * B0;
        float w1 = __expf(delta1 * a1) * hv1[q].y + dx1 * B1;
        float w2 = __expf(delta1 * a2) * hv1[q].z + dx1 * B2;
        float w3 = __expf(delta1 * a3) * hv1[q].w + dx1 * B3;
        acc1 += C0 * w0 + C1 * w1 + C2 * w2 + C3 * w3;
        hop1[q] = make_float4(w0, w1, w2, w3);
    }
    float yp0 = acc0 + Dv0 * xv0;
    float yp1 = acc1 + Dv1 * xv1;
    __half hh0 = __float2half_rn(yp0);
    __half hh1 = __float2half_rn(yp1);
    g_Yh[bd0] = *(uint16_t*)&hh0;
    g_Yh[bd1] = *(uint16_t*)&hh1;
}

// ---------------------------------------------------------------------------
// Unified HMMA GEMM: C[m,n] (+)= sum_k A[m,k]*B[n,k], 16-bit operands.
//   ASPLIT: A = Ah + Al. BSPLIT: adds Ah*Bl cross term.
// CTA 128x128, BK=32, 8 warps (2Mx4N), warp tile 64x32. 80B-padded SMEM rows.
// EPI: 0 = plain store, 1 = softplus(acc+bias[col]) store, 2 = guarded atomicAdd.
// Split-K via blockIdx.z. Requires niters >= NSTAGE-1.
// ---------------------------------------------------------------------------
#define ROW_B 80
#define TILE_B (128 * ROW_B)          // 10240

template<int DT, bool ASPLIT, bool BSPLIT, int EPI, int NSTAGE>
__global__ void __launch_bounds__(256, 1)
gemm16(const uint16_t* __restrict__ Ah, const uint16_t* __restrict__ Al,
       const uint16_t* __restrict__ Bh, const uint16_t* __restrict__ Bl,
       float* __restrict__ C, int ldc, int ldab, int niters,
       const float* __restrict__ bias, int n_real)
{
    constexpr int NTILES = 1 + (ASPLIT ? 1 : 0) + 1 + (BSPLIT ? 1 : 0);
    constexpr uint32_t OFF_A0 = 0;
    constexpr uint32_t OFF_A1 = ASPLIT ? TILE_B : 0;
    constexpr uint32_t OFF_B0 = (ASPLIT ? 2 : 1) * TILE_B;
    constexpr uint32_t OFF_B1 = (ASPLIT ? 3 : 2) * TILE_B;   // only if BSPLIT
    constexpr uint32_t STAGE = NTILES * TILE_B;

    extern __shared__ char smem[];
    const uint32_t sb = smem_u32(smem);
    const int tid = threadIdx.x;
    const int wid = tid >> 5;
    const int lane = tid & 31;
    const int warp_m = wid >> 2;
    const int warp_n = wid & 3;
    const int bm = blockIdx.x * 128;
    const int bn = blockIdx.y * 128;
    const int k_begin = blockIdx.z * niters * 32;

    auto load_stage = [&](uint32_t st, int k0) {
        #pragma unroll
        for (int cc = 0; cc < 2; cc++) {
            const int idx = tid + 256 * cc;
            const int row = idx >> 2;
            const int ch  = idx & 3;
            const uint32_t d = st + (uint32_t)(row * ROW_B + ch * 16);
            const int gk = k0 + ch * 8;
            cpasync16(d + OFF_A0, Ah + (size_t)(bm + row) * ldab + gk);
            if constexpr (ASPLIT)
                cpasync16(d + OFF_A1, Al + (size_t)(bm + row) * ldab + gk);
            cpasync16(d + OFF_B0, Bh + (size_t)(bn + row) * ldab + gk);
            if constexpr (BSPLIT)
                cpasync16(d + OFF_B1, Bl + (size_t)(bn + row) * ldab + gk);
        }
        cpasync_commit();
    };

    // ldmatrix per-lane byte offsets (within a tile, ks=0)
    uint32_t aoff[4], boff[2];
    #pragma unroll
    for (int mi = 0; mi < 4; mi++)
        aoff[mi] = (uint32_t)((warp_m * 64 + mi * 16 + (lane & 15)) * ROW_B + (lane >> 4) * 16);
    #pragma unroll
    for (int pi = 0; pi < 2; pi++) {
        int chunk = lane >> 3;
        int n = warp_n * 32 + pi * 16 + (chunk >> 1) * 8 + (lane & 7);
        boff[pi] = (uint32_t)(n * ROW_B + (chunk & 1) * 16);
    }

    float acc[4][4][4];
    #pragma unroll
    for (int mi = 0; mi < 4; mi++)
        #pragma unroll
        for (int ni = 0; ni < 4; ni++)
            #pragma unroll
            for (int q = 0; q < 4; q++) acc[mi][ni][q] = 0.0f;

    // prologue: stages 0..NSTAGE-2
    #pragma unroll
    for (int s = 0; s < NSTAGE - 1; s++)
        load_stage(sb + s * STAGE, k_begin + s * 32);

    for (int it = 0; it < niters; it++) {
        if (it + NSTAGE - 1 < niters)
            load_stage(sb + ((it + NSTAGE - 1) % NSTAGE) * STAGE,
                       k_begin + (it + NSTAGE - 1) * 32);
        else
            cpasync_commit();   // keep group count uniform
        asm volatile("cp.async.wait_group %0;" :: "n"(NSTAGE - 1) : "memory");
        __syncthreads();

        const uint32_t st = sb + (it % NSTAGE) * STAGE;
        #pragma unroll
        for (int ks = 0; ks < 2; ks++) {
            uint32_t a0[4][4], a1[4][4], b0[2][4], b1[2][4];
            #pragma unroll
            for (int mi = 0; mi < 4; mi++) {
                ldmatrix_x4(a0[mi], st + OFF_A0 + aoff[mi] + ks * 32);
                if constexpr (ASPLIT)
                    ldmatrix_x4(a1[mi], st + OFF_A1 + aoff[mi] + ks * 32);
            }
            #pragma unroll
            for (int pi = 0; pi < 2; pi++) {
                ldmatrix_x4(b0[pi], st + OFF_B0 + boff[pi] + ks * 32);
                if constexpr (BSPLIT)
                    ldmatrix_x4(b1[pi], st + OFF_B1 + boff[pi] + ks * 32);
            }
            #pragma unroll
            for (int mi = 0; mi < 4; mi++) {
                #pragma unroll
                for (int ni = 0; ni < 4; ni++) {
                    const int pi = ni >> 1;
                    const int sel = (ni & 1) * 2;
                    uint32_t bh[2] = {b0[pi][sel], b0[pi][sel + 1]};
                    mma16<DT>(acc[mi][ni], a0[mi], bh);
                    if constexpr (ASPLIT)
                        mma16<DT>(acc[mi][ni], a1[mi], bh);
                    if constexpr (BSPLIT) {
                        uint32_t bl[2] = {b1[pi][sel], b1[pi][sel + 1]};
                        mma16<DT>(acc[mi][ni], a0[mi], bl);
                    }
                }
            }
        }
        __syncthreads();
    }

    // epilogue
    #pragma unroll
    for (int mi = 0; mi < 4; mi++) {
        const int row = bm + warp_m * 64 + mi * 16 + (lane >> 2);
        #pragma unroll
        for (int ni = 0; ni < 4; ni++) {
            const int col = bn + warp_n * 32 + ni * 8 + (lane & 3) * 2;
            float* acc4 = acc[mi][ni];
            if constexpr (EPI == 0) {
                *(float2*)(C + (size_t)row * ldc + col) = make_float2(acc4[0], acc4[1]);
                *(float2*)(C + (size_t)(row + 8) * ldc + col) = make_float2(acc4[2], acc4[3]);
            } else if constexpr (EPI == 1) {
                float b0v = bias[col], b1v = bias[col + 1];
                *(float2*)(C + (size_t)row * ldc + col) =
                    make_float2(softplusf(acc4[0] + b0v), softplusf(acc4[1] + b1v));
                *(float2*)(C + (size_t)(row + 8) * ldc + col) =
                    make_float2(softplusf(acc4[2] + b0v), softplusf(acc4[3] + b1v));
            } else {
                if (col < n_real) {   // col even, n_real even -> covers col+1
                    atomicAdd(&C[(size_t)row * ldc + col],       acc4[0]);
                    atomicAdd(&C[(size_t)row * ldc + col + 1],   acc4[1]);
                    atomicAdd(&C[(size_t)(row + 8) * ldc + col],     acc4[2]);
                    atomicAdd(&C[(size_t)(row + 8) * ldc + col + 1], acc4[3]);
                }
            }
        }
    }
}

// ---------------------------------------------------------------------------
// Launch. Inputs: x, h, W_xproj, W_dt, b_dt, A_log, D, W_out.
// Output: [y (1024*4096), h_new (1024*4096*16)].
// ---------------------------------------------------------------------------
extern "C" void kernel_launch(void* const* d_in, const int* in_sizes, int n_in,
                              void* d_out, int out_size)
{
    const float* x    = (const float*)d_in[0];
    const float* h    = (const float*)d_in[1];
    const float* Wxp  = (const float*)d_in[2];
    const float* Wdt  = (const float*)d_in[3];
    const float* bdt  = (const float*)d_in[4];
    const float* Alog = (const float*)d_in[5];
    const float* Dv   = (const float*)d_in[6];
    const float* Wout = (const float*)d_in[7];

    float* y_out    = (float*)d_out;
    float* hnew_out = y_out + (size_t)BATCH * D_MODEL;

    float *xp_p, *delta_p;
    uint16_t *Wh16_p, *Yh_p, *xh_p, *xl_p, *Wxh_p, *Wxl_p, *dh_p, *dl_p, *Wdh_p, *Wdl_p;
    cudaGetSymbolAddress((void**)&xp_p, g_xp);
    cudaGetSymbolAddress((void**)&delta_p, g_delta);
    cudaGetSymbolAddress((void**)&Wh16_p, g_Wh16);
    cudaGetSymbolAddress((void**)&Yh_p, g_Yh);
    cudaGetSymbolAddress((void**)&xh_p, g_xh);
    cudaGetSymbolAddress((void**)&xl_p, g_xl);
    cudaGetSymbolAddress((void**)&Wxh_p, g_Wxh);
    cudaGetSymbolAddress((void**)&Wxl_p, g_Wxl);
    cudaGetSymbolAddress((void**)&dh_p, g_dh);
    cudaGetSymbolAddress((void**)&dl_p, g_dl);
    cudaGetSymbolAddress((void**)&Wdh_p, g_Wdh);
    cudaGetSymbolAddress((void**)&Wdl_p, g_Wdl);

    const int SMEM_G1 = 3 * 4 * TILE_B;   // 122880 (bf16x3: 4 tiles, 3 stages)
    const int SMEM_G2 = 4 * 4 * TILE_B;   // 163840 (bf16x3: 4 tiles, 4 stages)
    const int SMEM_G3 = 4 * 2 * TILE_B;   // 81920  (fp16x1: 2 tiles, 4 stages)
    cudaFuncSetAttribute((const void*)gemm16<0, true, true, 2, 3>,
                         cudaFuncAttributeMaxDynamicSharedMemorySize, SMEM_G1);
    cudaFuncSetAttribute((const void*)gemm16<0, true, true, 1, 4>,
                         cudaFuncAttributeMaxDynamicSharedMemorySize, SMEM_G2);
    cudaFuncSetAttribute((const void*)gemm16<1, false, false, 0, 4>,
                         cudaFuncAttributeMaxDynamicSharedMemorySize, SMEM_G3);

    // Operand preparation (separate kernels — measured-good configuration)
    conv_fp16_k<<<(D_MODEL * D_MODEL) / (4 * 256), 256>>>(Wout, Wh16_p);
    split_bf16_k<<<(BATCH * D_MODEL) / (4 * 256), 256>>>(x, xh_p, xl_p);
    split_wxproj_k<<<(WXP_PAD * D_MODEL) / (4 * 256), 256>>>(Wxp);
    split_bf16_k<<<(D_MODEL * DT_RANK) / (4 * 256), 256>>>(Wdt, Wdh_p, Wdl_p);
    zero_xp_kernel<<<(BATCH * XP_COLS + 255) / 256, 256>>>();

    // G1: xp = x @ W_xproj^T  (bf16x3 HMMA, split-K=8, 3-stage pipeline)
    gemm16<0, true, true, 2, 3><<<dim3(BATCH / 128, WXP_PAD / 128, 8), 256, SMEM_G1>>>(
        xh_p, xl_p, Wxh_p, Wxl_p, xp_p, XP_COLS, D_MODEL, (D_MODEL / 8) / 32,
        nullptr, XP_COLS);

    // delta_raw split (xp cols 0..255 -> bf16 hi/lo)
    split_xp_k<<<(BATCH * DT_RANK) / (4 * 256), 256>>>();

    // G2: delta = softplus(delta_raw @ W_dt^T + b_dt)  (bf16x3, 4-stage pipeline)
    gemm16<0, true, true, 1, 4><<<dim3(BATCH / 128, D_MODEL / 128, 1), 256, SMEM_G2>>>(
        dh_p, dl_p, Wdh_p, Wdl_p, delta_p, D_MODEL, DT_RANK, DT_RANK / 32,
        bdt, D_MODEL);

    // Standalone state update (2 d per thread -> MLP 8)
    state_update<<<dim3(D_MODEL / 512, BATCH), 256>>>(x, h, Alog, Dv, hnew_out);

    // G3: y = fp16(ypre) @ fp16(W_out)^T  (single product, 4-stage pipeline)
    gemm16<1, false, false, 0, 4><<<dim3(BATCH / 128, D_MODEL / 128, 1), 256, SMEM_G3>>>(
        Yh_p, nullptr, Wh16_p, nullptr, y_out, D_MODEL, D_MODEL, D_MODEL / 32,
        nullptr, D_MODEL);
}

// round 10
// speedup vs baseline: 1.4625x; 1.1042x over previous
#include <cuda_runtime.h>
#include <cuda_bf16.h>
#include <cuda_fp16.h>
#include <math.h>
#include <stdint.h>

#define BATCH   1024
#define D_MODEL 4096
#define D_STATE 16
#define DT_RANK 256
#define XP_COLS (DT_RANK + 2 * D_STATE)   // 288
#define WXP_PAD 384                        // 288 padded to 3 x 128

// ---------------- scratch (allocation-free rule: __device__ globals) --------
__device__ float g_xp[BATCH * XP_COLS];
__device__ float g_delta[BATCH * D_MODEL];
__device__ uint16_t g_Wh16[(size_t)D_MODEL * D_MODEL];   // fp16(W_out)
__device__ uint16_t g_Yh[(size_t)BATCH * D_MODEL];       // fp16(ypre)
__device__ uint16_t g_xh[(size_t)BATCH * D_MODEL];       // bf16 hi(x)
__device__ uint16_t g_xl[(size_t)BATCH * D_MODEL];       // bf16 lo(x)
__device__ uint16_t g_Wxh[(size_t)WXP_PAD * D_MODEL];    // bf16 hi(W_xproj), padded
__device__ uint16_t g_Wxl[(size_t)WXP_PAD * D_MODEL];
__device__ uint16_t g_dh[(size_t)BATCH * DT_RANK];       // bf16 hi(delta_raw)
__device__ uint16_t g_dl[(size_t)BATCH * DT_RANK];
__device__ uint16_t g_Wdh[(size_t)D_MODEL * DT_RANK];    // bf16 hi(W_dt)
__device__ uint16_t g_Wdl[(size_t)D_MODEL * DT_RANK];

__device__ __forceinline__ float softplusf(float z) {
    return (z > 20.0f) ? z : log1pf(__expf(z));
}

// ---------------- PTX helpers (sm_80-class only; no 'a'-target features) ----
__device__ __forceinline__ uint32_t smem_u32(const void* p) {
    uint32_t a;
    asm("{ .reg .u64 t; cvta.to.shared.u64 t, %1; cvt.u32.u64 %0, t; }" : "=r"(a) : "l"(p));
    return a;
}
__device__ __forceinline__ void cpasync16(uint32_t dst, const void* src) {
    asm volatile("cp.async.cg.shared.global [%0], [%1], 16;" :: "r"(dst), "l"(src));
}
__device__ __forceinline__ void cpasync_commit() {
    asm volatile("cp.async.commit_group;" ::: "memory");
}
__device__ __forceinline__ void ldmatrix_x4(uint32_t* r, uint32_t addr) {
    asm volatile("ldmatrix.sync.aligned.m8n8.x4.shared.b16 {%0,%1,%2,%3}, [%4];"
                 : "=r"(r[0]), "=r"(r[1]), "=r"(r[2]), "=r"(r[3]) : "r"(addr));
}
// DT: 0 = bf16, 1 = fp16
template<int DT>
__device__ __forceinline__ void mma16(float* c, const uint32_t* a, const uint32_t* b) {
    if constexpr (DT == 0) {
        asm volatile(
            "mma.sync.aligned.m16n8k16.row.col.f32.bf16.bf16.f32 "
            "{%0,%1,%2,%3}, {%4,%5,%6,%7}, {%8,%9}, {%0,%1,%2,%3};"
            : "+f"(c[0]), "+f"(c[1]), "+f"(c[2]), "+f"(c[3])
            : "r"(a[0]), "r"(a[1]), "r"(a[2]), "r"(a[3]), "r"(b[0]), "r"(b[1]));
    } else {
        asm volatile(
            "mma.sync.aligned.m16n8k16.row.col.f32.f16.f16.f32 "
            "{%0,%1,%2,%3}, {%4,%5,%6,%7}, {%8,%9}, {%0,%1,%2,%3};"
            : "+f"(c[0]), "+f"(c[1]), "+f"(c[2]), "+f"(c[3])
            : "r"(a[0]), "r"(a[1]), "r"(a[2]), "r"(a[3]), "r"(b[0]), "r"(b[1]));
    }
}

// ---------------------------------------------------------------------------
// Conversion / split kernels (round-6 measured-good configuration)
// ---------------------------------------------------------------------------
__global__ void zero_xp_kernel() {
    int i = blockIdx.x * blockDim.x + threadIdx.x;
    if (i < BATCH * XP_COLS) g_xp[i] = 0.0f;
}

__device__ __forceinline__ void split4_bf16(const float* vv, uint16_t* h, uint16_t* l, size_t i) {
    #pragma unroll
    for (int q = 0; q < 4; q++) {
        __nv_bfloat16 hi = __float2bfloat16(vv[q]);
        __nv_bfloat16 lo = __float2bfloat16(vv[q] - __bfloat162float(hi));
        h[i + q] = *(uint16_t*)&hi;
        l[i + q] = *(uint16_t*)&lo;
    }
}

__global__ void __launch_bounds__(256)
split_bf16_k(const float* __restrict__ in, uint16_t* __restrict__ h, uint16_t* __restrict__ l) {
    size_t i = ((size_t)blockIdx.x * blockDim.x + threadIdx.x) * 4;
    float4 v = *(const float4*)(in + i);
    float vv[4] = {v.x, v.y, v.z, v.w};
    split4_bf16(vv, h, l, i);
}

__global__ void __launch_bounds__(256)
conv_fp16_k(const float* __restrict__ in, uint16_t* __restrict__ out) {
    size_t i = ((size_t)blockIdx.x * blockDim.x + threadIdx.x) * 4;
    float4 v = *(const float4*)(in + i);
    __half h0 = __float2half_rn(v.x), h1 = __float2half_rn(v.y);
    __half h2 = __float2half_rn(v.z), h3 = __float2half_rn(v.w);
    uint16_t* o = out + i;
    o[0] = *(uint16_t*)&h0; o[1] = *(uint16_t*)&h1;
    o[2] = *(uint16_t*)&h2; o[3] = *(uint16_t*)&h3;
}

__global__ void __launch_bounds__(256)
split_wxproj_k(const float* __restrict__ in) {
    size_t i = ((size_t)blockIdx.x * blockDim.x + threadIdx.x) * 4;   // over 384*4096
    int row = (int)(i >> 12);
    float vv[4] = {0.f, 0.f, 0.f, 0.f};
    if (row < XP_COLS) {
        float4 v = *(const float4*)(in + i);
        vv[0] = v.x; vv[1] = v.y; vv[2] = v.z; vv[3] = v.w;
    }
    split4_bf16(vv, g_Wxh, g_Wxl, i);
}

__global__ void __launch_bounds__(256)
split_xp_k() {
    size_t i = ((size_t)blockIdx.x * blockDim.x + threadIdx.x) * 4;   // over 1024*256
    int row = (int)(i >> 8);
    int col = (int)(i & 255);
    float4 v = *(const float4*)(g_xp + (size_t)row * XP_COLS + col);
    float vv[4] = {v.x, v.y, v.z, v.w};
    split4_bf16(vv, g_dh, g_dl, i);
}

// ---------------------------------------------------------------------------
// Standalone fused state update (round-6 configuration: 1 d per thread,
// 16384 CTAs, plain loads/stores).
// ---------------------------------------------------------------------------
__global__ void __launch_bounds__(256)
state_update(const float* __restrict__ x,
             const float* __restrict__ h,
             const float* __restrict__ A_log,
             const float* __restrict__ Dv,
             float* __restrict__ h_new)
{
    __shared__ float sA[D_STATE], sB[D_STATE], sC[D_STATE];
    const int b = blockIdx.y;
    const int d = blockIdx.x * blockDim.x + threadIdx.x;

    if (threadIdx.x < D_STATE) {
        int n = threadIdx.x;
        sA[n] = -expf(A_log[n]);
        sB[n] = g_xp[(size_t)b * XP_COLS + DT_RANK + n];
        sC[n] = g_xp[(size_t)b * XP_COLS + DT_RANK + D_STATE + n];
    }
    __syncthreads();

    const size_t bd = (size_t)b * D_MODEL + d;
    const float delta = g_delta[bd];
    const float xv = x[bd];
    const float dx = delta * xv;

    const float4* hp = (const float4*)(h + bd * D_STATE);
    float4* hop = (float4*)(h_new + bd * D_STATE);

    float acc = 0.0f;
    #pragma unroll
    for (int q = 0; q < 4; q++) {
        float4 hv = hp[q];
        float h0 = __expf(delta * sA[4 * q + 0]) * hv.x + dx * sB[4 * q + 0];
        float h1 = __expf(delta * sA[4 * q + 1]) * hv.y + dx * sB[4 * q + 1];
        float h2 = __expf(delta * sA[4 * q + 2]) * hv.z + dx * sB[4 * q + 2];
        float h3 = __expf(delta * sA[4 * q + 3]) * hv.w + dx * sB[4 * q + 3];
        acc += sC[4 * q + 0] * h0 + sC[4 * q + 1] * h1
             + sC[4 * q + 2] * h2 + sC[4 * q + 3] * h3;
        hop[q] = make_float4(h0, h1, h2, h3);
    }
    float ypre = acc + Dv[d] * xv;
    __half hi = __float2half_rn(ypre);
    g_Yh[bd] = *(uint16_t*)&hi;
}

// ---------------------------------------------------------------------------
// Unified HMMA GEMM: C[m,n] (+)= sum_k A[m,k]*B[n,k], 16-bit operands.
//   ASPLIT: A = Ah + Al. BSPLIT: adds Ah*Bl cross term.
// CTA 128x128, BK=32, 8 warps (2Mx4N), warp tile 64x32. 80B-padded SMEM rows.
// EPI: 0 = plain store, 1 = softplus(acc+bias[col]) store, 2 = guarded atomicAdd.
// OCC: min blocks/SM for __launch_bounds__ (2 -> <=128 regs, co-resident CTAs).
// ---------------------------------------------------------------------------
#define ROW_B 80
#define TILE_B (128 * ROW_B)          // 10240

template<int DT, bool ASPLIT, bool BSPLIT, int EPI, int NSTAGE, int OCC>
__global__ void __launch_bounds__(256, OCC)
gemm16(const uint16_t* __restrict__ Ah, const uint16_t* __restrict__ Al,
       const uint16_t* __restrict__ Bh, const uint16_t* __restrict__ Bl,
       float* __restrict__ C, int ldc, int ldab, int niters,
       const float* __restrict__ bias, int n_real)
{
    constexpr int NTILES = 1 + (ASPLIT ? 1 : 0) + 1 + (BSPLIT ? 1 : 0);
    constexpr uint32_t OFF_A0 = 0;
    constexpr uint32_t OFF_A1 = ASPLIT ? TILE_B : 0;
    constexpr uint32_t OFF_B0 = (ASPLIT ? 2 : 1) * TILE_B;
    constexpr uint32_t OFF_B1 = (ASPLIT ? 3 : 2) * TILE_B;   // only if BSPLIT
    constexpr uint32_t STAGE = NTILES * TILE_B;

    extern __shared__ char smem[];
    const uint32_t sb = smem_u32(smem);
    const int tid = threadIdx.x;
    const int wid = tid >> 5;
    const int lane = tid & 31;
    const int warp_m = wid >> 2;
    const int warp_n = wid & 3;
    const int bm = blockIdx.x * 128;
    const int bn = blockIdx.y * 128;
    const int k_begin = blockIdx.z * niters * 32;

    auto load_stage = [&](uint32_t st, int k0) {
        #pragma unroll
        for (int cc = 0; cc < 2; cc++) {
            const int idx = tid + 256 * cc;
            const int row = idx >> 2;
            const int ch  = idx & 3;
            const uint32_t d = st + (uint32_t)(row * ROW_B + ch * 16);
            const int gk = k0 + ch * 8;
            cpasync16(d + OFF_A0, Ah + (size_t)(bm + row) * ldab + gk);
            if constexpr (ASPLIT)
                cpasync16(d + OFF_A1, Al + (size_t)(bm + row) * ldab + gk);
            cpasync16(d + OFF_B0, Bh + (size_t)(bn + row) * ldab + gk);
            if constexpr (BSPLIT)
                cpasync16(d + OFF_B1, Bl + (size_t)(bn + row) * ldab + gk);
        }
        cpasync_commit();
    };

    // ldmatrix per-lane byte offsets (within a tile, ks=0)
    uint32_t aoff[4], boff[2];
    #pragma unroll
    for (int mi = 0; mi < 4; mi++)
        aoff[mi] = (uint32_t)((warp_m * 64 + mi * 16 + (lane & 15)) * ROW_B + (lane >> 4) * 16);
    #pragma unroll
    for (int pi = 0; pi < 2; pi++) {
        int chunk = lane >> 3;
        int n = warp_n * 32 + pi * 16 + (chunk >> 1) * 8 + (lane & 7);
        boff[pi] = (uint32_t)(n * ROW_B + (chunk & 1) * 16);
    }

    float acc[4][4][4];
    #pragma unroll
    for (int mi = 0; mi < 4; mi++)
        #pragma unroll
        for (int ni = 0; ni < 4; ni++)
            #pragma unroll
            for (int q = 0; q < 4; q++) acc[mi][ni][q] = 0.0f;

    // prologue: stages 0..NSTAGE-2
    #pragma unroll
    for (int s = 0; s < NSTAGE - 1; s++)
        load_stage(sb + s * STAGE, k_begin + s * 32);

    for (int it = 0; it < niters; it++) {
        if (it + NSTAGE - 1 < niters)
            load_stage(sb + ((it + NSTAGE - 1) % NSTAGE) * STAGE,
                       k_begin + (it + NSTAGE - 1) * 32);
        else
            cpasync_commit();   // keep group count uniform
        asm volatile("cp.async.wait_group %0;" :: "n"(NSTAGE - 1) : "memory");
        __syncthreads();

        const uint32_t st = sb + (it % NSTAGE) * STAGE;
        #pragma unroll
        for (int ks = 0; ks < 2; ks++) {
            uint32_t a0[4][4], a1[4][4], b0[2][4], b1[2][4];
            #pragma unroll
            for (int mi = 0; mi < 4; mi++) {
                ldmatrix_x4(a0[mi], st + OFF_A0 + aoff[mi] + ks * 32);
                if constexpr (ASPLIT)
                    ldmatrix_x4(a1[mi], st + OFF_A1 + aoff[mi] + ks * 32);
            }
            #pragma unroll
            for (int pi = 0; pi < 2; pi++) {
                ldmatrix_x4(b0[pi], st + OFF_B0 + boff[pi] + ks * 32);
                if constexpr (BSPLIT)
                    ldmatrix_x4(b1[pi], st + OFF_B1 + boff[pi] + ks * 32);
            }
            #pragma unroll
            for (int mi = 0; mi < 4; mi++) {
                #pragma unroll
                for (int ni = 0; ni < 4; ni++) {
                    const int pi = ni >> 1;
                    const int sel = (ni & 1) * 2;
                    uint32_t bh[2] = {b0[pi][sel], b0[pi][sel + 1]};
                    mma16<DT>(acc[mi][ni], a0[mi], bh);
                    if constexpr (ASPLIT)
                        mma16<DT>(acc[mi][ni], a1[mi], bh);
                    if constexpr (BSPLIT) {
                        uint32_t bl[2] = {b1[pi][sel], b1[pi][sel + 1]};
                        mma16<DT>(acc[mi][ni], a0[mi], bl);
                    }
                }
            }
        }
        __syncthreads();
    }

    // epilogue
    #pragma unroll
    for (int mi = 0; mi < 4; mi++) {
        const int row = bm + warp_m * 64 + mi * 16 + (lane >> 2);
        #pragma unroll
        for (int ni = 0; ni < 4; ni++) {
            const int col = bn + warp_n * 32 + ni * 8 + (lane & 3) * 2;
            float* acc4 = acc[mi][ni];
            if constexpr (EPI == 0) {
                *(float2*)(C + (size_t)row * ldc + col) = make_float2(acc4[0], acc4[1]);
                *(float2*)(C + (size_t)(row + 8) * ldc + col) = make_float2(acc4[2], acc4[3]);
            } else if constexpr (EPI == 1) {
                float b0v = bias[col], b1v = bias[col + 1];
                *(float2*)(C + (size_t)row * ldc + col) =
                    make_float2(softplusf(acc4[0] + b0v), softplusf(acc4[1] + b1v));
                *(float2*)(C + (size_t)(row + 8) * ldc + col) =
                    make_float2(softplusf(acc4[2] + b0v), softplusf(acc4[3] + b1v));
            } else {
                if (col < n_real) {   // col even, n_real even -> covers col+1
                    atomicAdd(&C[(size_t)row * ldc + col],       acc4[0]);
                    atomicAdd(&C[(size_t)row * ldc + col + 1],   acc4[1]);
                    atomicAdd(&C[(size_t)(row + 8) * ldc + col],     acc4[2]);
                    atomicAdd(&C[(size_t)(row + 8) * ldc + col + 1], acc4[3]);
                }
            }
        }
    }
}

// ---------------------------------------------------------------------------
// Launch. Inputs: x, h, W_xproj, W_dt, b_dt, A_log, D, W_out.
// Output: [y (1024*4096), h_new (1024*4096*16)].
// ---------------------------------------------------------------------------
extern "C" void kernel_launch(void* const* d_in, const int* in_sizes, int n_in,
                              void* d_out, int out_size)
{
    const float* x    = (const float*)d_in[0];
    const float* h    = (const float*)d_in[1];
    const float* Wxp  = (const float*)d_in[2];
    const float* Wdt  = (const float*)d_in[3];
    const float* bdt  = (const float*)d_in[4];
    const float* Alog = (const float*)d_in[5];
    const float* Dv   = (const float*)d_in[6];
    const float* Wout = (const float*)d_in[7];

    float* y_out    = (float*)d_out;
    float* hnew_out = y_out + (size_t)BATCH * D_MODEL;

    float *xp_p, *delta_p;
    uint16_t *Wh16_p, *Yh_p, *xh_p, *xl_p, *Wxh_p, *Wxl_p, *dh_p, *dl_p, *Wdh_p, *Wdl_p;
    cudaGetSymbolAddress((void**)&xp_p, g_xp);
    cudaGetSymbolAddress((void**)&delta_p, g_delta);
    cudaGetSymbolAddress((void**)&Wh16_p, g_Wh16);
    cudaGetSymbolAddress((void**)&Yh_p, g_Yh);
    cudaGetSymbolAddress((void**)&xh_p, g_xh);
    cudaGetSymbolAddress((void**)&xl_p, g_xl);
    cudaGetSymbolAddress((void**)&Wxh_p, g_Wxh);
    cudaGetSymbolAddress((void**)&Wxl_p, g_Wxl);
    cudaGetSymbolAddress((void**)&dh_p, g_dh);
    cudaGetSymbolAddress((void**)&dl_p, g_dl);
    cudaGetSymbolAddress((void**)&Wdh_p, g_Wdh);
    cudaGetSymbolAddress((void**)&Wdl_p, g_Wdl);

    const int SMEM4 = 2 * 4 * TILE_B;   // 81920  (bf16x3: 4 tiles, 2 stages)
    const int SMEM2 = 4 * 2 * TILE_B;   // 81920  (fp16x1: 2 tiles, 4 stages)
    cudaFuncSetAttribute((const void*)gemm16<0, true, true, 2, 2, 1>,
                         cudaFuncAttributeMaxDynamicSharedMemorySize, SMEM4);
    cudaFuncSetAttribute((const void*)gemm16<0, true, true, 1, 2, 1>,
                         cudaFuncAttributeMaxDynamicSharedMemorySize, SMEM4);
    cudaFuncSetAttribute((const void*)gemm16<1, false, false, 0, 4, 2>,
                         cudaFuncAttributeMaxDynamicSharedMemorySize, SMEM2);

    // Operand preparation (round-6 measured-good configuration)
    conv_fp16_k<<<(D_MODEL * D_MODEL) / (4 * 256), 256>>>(Wout, Wh16_p);
    split_bf16_k<<<(BATCH * D_MODEL) / (4 * 256), 256>>>(x, xh_p, xl_p);
    split_wxproj_k<<<(WXP_PAD * D_MODEL) / (4 * 256), 256>>>(Wxp);
    split_bf16_k<<<(D_MODEL * DT_RANK) / (4 * 256), 256>>>(Wdt, Wdh_p, Wdl_p);
    zero_xp_kernel<<<(BATCH * XP_COLS + 255) / 256, 256>>>();

    // G1: xp = x @ W_xproj^T  (bf16x3 HMMA, split-K=8, 2-stage)
    gemm16<0, true, true, 2, 2, 1><<<dim3(BATCH / 128, WXP_PAD / 128, 8), 256, SMEM4>>>(
        xh_p, xl_p, Wxh_p, Wxl_p, xp_p, XP_COLS, D_MODEL, (D_MODEL / 8) / 32,
        nullptr, XP_COLS);

    // delta_raw split (xp cols 0..255 -> bf16 hi/lo)
    split_xp_k<<<(BATCH * DT_RANK) / (4 * 256), 256>>>();

    // G2: delta = softplus(delta_raw @ W_dt^T + b_dt)  (bf16x3, 2-stage)
    gemm16<0, true, true, 1, 2, 1><<<dim3(BATCH / 128, D_MODEL / 128, 1), 256, SMEM4>>>(
        dh_p, dl_p, Wdh_p, Wdl_p, delta_p, D_MODEL, DT_RANK, DT_RANK / 32,
        bdt, D_MODEL);

    // Standalone state update (round-6 configuration)
    state_update<<<dim3(D_MODEL / 256, BATCH), 256>>>(x, h, Alog, Dv, hnew_out);

    // G3: y = fp16(ypre) @ fp16(W_out)^T  (single product, 4-stage,
    //     occupancy 2 -> all 256 CTAs co-resident, no wave-2 idle tail)
    gemm16<1, false, false, 0, 4, 2><<<dim3(BATCH / 128, D_MODEL / 128, 1), 256, SMEM2>>>(
        Yh_p, nullptr, Wh16_p, nullptr, y_out, D_MODEL, D_MODEL, D_MODEL / 32,
        nullptr, D_MODEL);
}

// round 11
// speedup vs baseline: 1.5110x; 1.0332x over previous
#include <cuda_runtime.h>
#include <cuda_bf16.h>
#include <cuda_fp16.h>
#include <math.h>
#include <stdint.h>

#define BATCH   1024
#define D_MODEL 4096
#define D_STATE 16
#define DT_RANK 256
#define XP_COLS (DT_RANK + 2 * D_STATE)   // 288
#define WXP_PAD 384                        // 288 padded to 3 x 128

// ---------------- scratch (allocation-free rule: __device__ globals) --------
__device__ float g_xp[BATCH * XP_COLS];
__device__ float g_delta[BATCH * D_MODEL];
__device__ uint16_t g_Wh16[(size_t)D_MODEL * D_MODEL];   // fp16(W_out)
__device__ uint16_t g_Yh[(size_t)BATCH * D_MODEL];       // fp16(ypre)
__device__ uint16_t g_xh[(size_t)BATCH * D_MODEL];       // bf16 hi(x)
__device__ uint16_t g_xl[(size_t)BATCH * D_MODEL];       // bf16 lo(x)
__device__ uint16_t g_Wxh[(size_t)WXP_PAD * D_MODEL];    // bf16 hi(W_xproj), padded
__device__ uint16_t g_Wxl[(size_t)WXP_PAD * D_MODEL];
__device__ uint16_t g_dh[(size_t)BATCH * DT_RANK];       // bf16 hi(delta_raw)
__device__ uint16_t g_dl[(size_t)BATCH * DT_RANK];
__device__ uint16_t g_Wdh[(size_t)D_MODEL * DT_RANK];    // bf16 hi(W_dt)
__device__ uint16_t g_Wdl[(size_t)D_MODEL * DT_RANK];

__device__ __forceinline__ float softplusf(float z) {
    return (z > 20.0f) ? z : log1pf(__expf(z));
}

// ---------------- PTX helpers (sm_80-class only; no 'a'-target features) ----
__device__ __forceinline__ uint32_t smem_u32(const void* p) {
    uint32_t a;
    asm("{ .reg .u64 t; cvta.to.shared.u64 t, %1; cvt.u32.u64 %0, t; }" : "=r"(a) : "l"(p));
    return a;
}
__device__ __forceinline__ void cpasync16(uint32_t dst, const void* src) {
    asm volatile("cp.async.cg.shared.global [%0], [%1], 16;" :: "r"(dst), "l"(src));
}
__device__ __forceinline__ void cpasync_commit() {
    asm volatile("cp.async.commit_group;" ::: "memory");
}
__device__ __forceinline__ void ldmatrix_x4(uint32_t* r, uint32_t addr) {
    asm volatile("ldmatrix.sync.aligned.m8n8.x4.shared.b16 {%0,%1,%2,%3}, [%4];"
                 : "=r"(r[0]), "=r"(r[1]), "=r"(r[2]), "=r"(r[3]) : "r"(addr));
}
// DT: 0 = bf16, 1 = fp16
template<int DT>
__device__ __forceinline__ void mma16(float* c, const uint32_t* a, const uint32_t* b) {
    if constexpr (DT == 0) {
        asm volatile(
            "mma.sync.aligned.m16n8k16.row.col.f32.bf16.bf16.f32 "
            "{%0,%1,%2,%3}, {%4,%5,%6,%7}, {%8,%9}, {%0,%1,%2,%3};"
            : "+f"(c[0]), "+f"(c[1]), "+f"(c[2]), "+f"(c[3])
            : "r"(a[0]), "r"(a[1]), "r"(a[2]), "r"(a[3]), "r"(b[0]), "r"(b[1]));
    } else {
        asm volatile(
            "mma.sync.aligned.m16n8k16.row.col.f32.f16.f16.f32 "
            "{%0,%1,%2,%3}, {%4,%5,%6,%7}, {%8,%9}, {%0,%1,%2,%3};"
            : "+f"(c[0]), "+f"(c[1]), "+f"(c[2]), "+f"(c[3])
            : "r"(a[0]), "r"(a[1]), "r"(a[2]), "r"(a[3]), "r"(b[0]), "r"(b[1]));
    }
}

// ---------------------------------------------------------------------------
// Conversion / split kernels (measured-good configuration)
// ---------------------------------------------------------------------------
__global__ void zero_xp_kernel() {
    int i = blockIdx.x * blockDim.x + threadIdx.x;
    if (i < BATCH * XP_COLS) g_xp[i] = 0.0f;
}

__device__ __forceinline__ void split4_bf16(const float* vv, uint16_t* h, uint16_t* l, size_t i) {
    #pragma unroll
    for (int q = 0; q < 4; q++) {
        __nv_bfloat16 hi = __float2bfloat16(vv[q]);
        __nv_bfloat16 lo = __float2bfloat16(vv[q] - __bfloat162float(hi));
        h[i + q] = *(uint16_t*)&hi;
        l[i + q] = *(uint16_t*)&lo;
    }
}

__global__ void __launch_bounds__(256)
split_bf16_k(const float* __restrict__ in, uint16_t* __restrict__ h, uint16_t* __restrict__ l) {
    size_t i = ((size_t)blockIdx.x * blockDim.x + threadIdx.x) * 4;
    float4 v = *(const float4*)(in + i);
    float vv[4] = {v.x, v.y, v.z, v.w};
    split4_bf16(vv, h, l, i);
}

__global__ void __launch_bounds__(256)
conv_fp16_k(const float* __restrict__ in, uint16_t* __restrict__ out) {
    size_t i = ((size_t)blockIdx.x * blockDim.x + threadIdx.x) * 4;
    float4 v = *(const float4*)(in + i);
    __half h0 = __float2half_rn(v.x), h1 = __float2half_rn(v.y);
    __half h2 = __float2half_rn(v.z), h3 = __float2half_rn(v.w);
    uint16_t* o = out + i;
    o[0] = *(uint16_t*)&h0; o[1] = *(uint16_t*)&h1;
    o[2] = *(uint16_t*)&h2; o[3] = *(uint16_t*)&h3;
}

__global__ void __launch_bounds__(256)
split_wxproj_k(const float* __restrict__ in) {
    size_t i = ((size_t)blockIdx.x * blockDim.x + threadIdx.x) * 4;   // over 384*4096
    int row = (int)(i >> 12);
    float vv[4] = {0.f, 0.f, 0.f, 0.f};
    if (row < XP_COLS) {
        float4 v = *(const float4*)(in + i);
        vv[0] = v.x; vv[1] = v.y; vv[2] = v.z; vv[3] = v.w;
    }
    split4_bf16(vv, g_Wxh, g_Wxl, i);
}

__global__ void __launch_bounds__(256)
split_xp_k() {
    size_t i = ((size_t)blockIdx.x * blockDim.x + threadIdx.x) * 4;   // over 1024*256
    int row = (int)(i >> 8);
    int col = (int)(i & 255);
    float4 v = *(const float4*)(g_xp + (size_t)row * XP_COLS + col);
    float vv[4] = {v.x, v.y, v.z, v.w};
    split4_bf16(vv, g_dh, g_dl, i);
}

// ---------------------------------------------------------------------------
// Standalone fused state update (measured-good: 1 d per thread, 16384 CTAs).
// ---------------------------------------------------------------------------
__global__ void __launch_bounds__(256)
state_update(const float* __restrict__ x,
             const float* __restrict__ h,
             const float* __restrict__ A_log,
             const float* __restrict__ Dv,
             float* __restrict__ h_new)
{
    __shared__ float sA[D_STATE], sB[D_STATE], sC[D_STATE];
    const int b = blockIdx.y;
    const int d = blockIdx.x * blockDim.x + threadIdx.x;

    if (threadIdx.x < D_STATE) {
        int n = threadIdx.x;
        sA[n] = -expf(A_log[n]);
        sB[n] = g_xp[(size_t)b * XP_COLS + DT_RANK + n];
        sC[n] = g_xp[(size_t)b * XP_COLS + DT_RANK + D_STATE + n];
    }
    __syncthreads();

    const size_t bd = (size_t)b * D_MODEL + d;
    const float delta = g_delta[bd];
    const float xv = x[bd];
    const float dx = delta * xv;

    const float4* hp = (const float4*)(h + bd * D_STATE);
    float4* hop = (float4*)(h_new + bd * D_STATE);

    float acc = 0.0f;
    #pragma unroll
    for (int q = 0; q < 4; q++) {
        float4 hv = hp[q];
        float h0 = __expf(delta * sA[4 * q + 0]) * hv.x + dx * sB[4 * q + 0];
        float h1 = __expf(delta * sA[4 * q + 1]) * hv.y + dx * sB[4 * q + 1];
        float h2 = __expf(delta * sA[4 * q + 2]) * hv.z + dx * sB[4 * q + 2];
        float h3 = __expf(delta * sA[4 * q + 3]) * hv.w + dx * sB[4 * q + 3];
        acc += sC[4 * q + 0] * h0 + sC[4 * q + 1] * h1
             + sC[4 * q + 2] * h2 + sC[4 * q + 3] * h3;
        hop[q] = make_float4(h0, h1, h2, h3);
    }
    float ypre = acc + Dv[d] * xv;
    __half hi = __float2half_rn(ypre);
    g_Yh[bd] = *(uint16_t*)&hi;
}

// ---------------------------------------------------------------------------
// Unified HMMA GEMM: C[m,n] (+)= sum_k A[m,k]*B[n,k], 16-bit operands.
//   ASPLIT: A = Ah + Al. BSPLIT: adds Ah*Bl cross term.
// CTA 128x128, BK=32, 8 warps (2Mx4N), warp tile 64x32. 80B-padded SMEM rows.
// EPI: 0 = plain store, 1 = softplus(acc+bias[col]) store, 2 = guarded atomicAdd.
// OCC: min blocks/SM (2 -> <=128 regs, co-resident CTAs, single wave).
// ---------------------------------------------------------------------------
#define ROW_B 80
#define TILE_B (128 * ROW_B)          // 10240

template<int DT, bool ASPLIT, bool BSPLIT, int EPI, int NSTAGE, int OCC>
__global__ void __launch_bounds__(256, OCC)
gemm16(const uint16_t* __restrict__ Ah, const uint16_t* __restrict__ Al,
       const uint16_t* __restrict__ Bh, const uint16_t* __restrict__ Bl,
       float* __restrict__ C, int ldc, int ldab, int niters,
       const float* __restrict__ bias, int n_real)
{
    constexpr int NTILES = 1 + (ASPLIT ? 1 : 0) + 1 + (BSPLIT ? 1 : 0);
    constexpr uint32_t OFF_A0 = 0;
    constexpr uint32_t OFF_A1 = ASPLIT ? TILE_B : 0;
    constexpr uint32_t OFF_B0 = (ASPLIT ? 2 : 1) * TILE_B;
    constexpr uint32_t OFF_B1 = (ASPLIT ? 3 : 2) * TILE_B;   // only if BSPLIT
    constexpr uint32_t STAGE = NTILES * TILE_B;

    extern __shared__ char smem[];
    const uint32_t sb = smem_u32(smem);
    const int tid = threadIdx.x;
    const int wid = tid >> 5;
    const int lane = tid & 31;
    const int warp_m = wid >> 2;
    const int warp_n = wid & 3;
    const int bm = blockIdx.x * 128;
    const int bn = blockIdx.y * 128;
    const int k_begin = blockIdx.z * niters * 32;

    auto load_stage = [&](uint32_t st, int k0) {
        #pragma unroll
        for (int cc = 0; cc < 2; cc++) {
            const int idx = tid + 256 * cc;
            const int row = idx >> 2;
            const int ch  = idx & 3;
            const uint32_t d = st + (uint32_t)(row * ROW_B + ch * 16);
            const int gk = k0 + ch * 8;
            cpasync16(d + OFF_A0, Ah + (size_t)(bm + row) * ldab + gk);
            if constexpr (ASPLIT)
                cpasync16(d + OFF_A1, Al + (size_t)(bm + row) * ldab + gk);
            cpasync16(d + OFF_B0, Bh + (size_t)(bn + row) * ldab + gk);
            if constexpr (BSPLIT)
                cpasync16(d + OFF_B1, Bl + (size_t)(bn + row) * ldab + gk);
        }
        cpasync_commit();
    };

    // ldmatrix per-lane byte offsets (within a tile, ks=0)
    uint32_t aoff[4], boff[2];
    #pragma unroll
    for (int mi = 0; mi < 4; mi++)
        aoff[mi] = (uint32_t)((warp_m * 64 + mi * 16 + (lane & 15)) * ROW_B + (lane >> 4) * 16);
    #pragma unroll
    for (int pi = 0; pi < 2; pi++) {
        int chunk = lane >> 3;
        int n = warp_n * 32 + pi * 16 + (chunk >> 1) * 8 + (lane & 7);
        boff[pi] = (uint32_t)(n * ROW_B + (chunk & 1) * 16);
    }

    float acc[4][4][4];
    #pragma unroll
    for (int mi = 0; mi < 4; mi++)
        #pragma unroll
        for (int ni = 0; ni < 4; ni++)
            #pragma unroll
            for (int q = 0; q < 4; q++) acc[mi][ni][q] = 0.0f;

    // prologue: stages 0..NSTAGE-2
    #pragma unroll
    for (int s = 0; s < NSTAGE - 1; s++)
        load_stage(sb + s * STAGE, k_begin + s * 32);

    for (int it = 0; it < niters; it++) {
        if (it + NSTAGE - 1 < niters)
            load_stage(sb + ((it + NSTAGE - 1) % NSTAGE) * STAGE,
                       k_begin + (it + NSTAGE - 1) * 32);
        else
            cpasync_commit();   // keep group count uniform
        asm volatile("cp.async.wait_group %0;" :: "n"(NSTAGE - 1) : "memory");
        __syncthreads();

        const uint32_t st = sb + (it % NSTAGE) * STAGE;
        #pragma unroll
        for (int ks = 0; ks < 2; ks++) {
            uint32_t a0[4][4], a1[4][4], b0[2][4], b1[2][4];
            #pragma unroll
            for (int mi = 0; mi < 4; mi++) {
                ldmatrix_x4(a0[mi], st + OFF_A0 + aoff[mi] + ks * 32);
                if constexpr (ASPLIT)
                    ldmatrix_x4(a1[mi], st + OFF_A1 + aoff[mi] + ks * 32);
            }
            #pragma unroll
            for (int pi = 0; pi < 2; pi++) {
                ldmatrix_x4(b0[pi], st + OFF_B0 + boff[pi] + ks * 32);
                if constexpr (BSPLIT)
                    ldmatrix_x4(b1[pi], st + OFF_B1 + boff[pi] + ks * 32);
            }
            #pragma unroll
            for (int mi = 0; mi < 4; mi++) {
                #pragma unroll
                for (int ni = 0; ni < 4; ni++) {
                    const int pi = ni >> 1;
                    const int sel = (ni & 1) * 2;
                    uint32_t bh[2] = {b0[pi][sel], b0[pi][sel + 1]};
                    mma16<DT>(acc[mi][ni], a0[mi], bh);
                    if constexpr (ASPLIT)
                        mma16<DT>(acc[mi][ni], a1[mi], bh);
                    if constexpr (BSPLIT) {
                        uint32_t bl[2] = {b1[pi][sel], b1[pi][sel + 1]};
                        mma16<DT>(acc[mi][ni], a0[mi], bl);
                    }
                }
            }
        }
        __syncthreads();
    }

    // epilogue
    #pragma unroll
    for (int mi = 0; mi < 4; mi++) {
        const int row = bm + warp_m * 64 + mi * 16 + (lane >> 2);
        #pragma unroll
        for (int ni = 0; ni < 4; ni++) {
            const int col = bn + warp_n * 32 + ni * 8 + (lane & 3) * 2;
            float* acc4 = acc[mi][ni];
            if constexpr (EPI == 0) {
                *(float2*)(C + (size_t)row * ldc + col) = make_float2(acc4[0], acc4[1]);
                *(float2*)(C + (size_t)(row + 8) * ldc + col) = make_float2(acc4[2], acc4[3]);
            } else if constexpr (EPI == 1) {
                float b0v = bias[col], b1v = bias[col + 1];
                *(float2*)(C + (size_t)row * ldc + col) =
                    make_float2(softplusf(acc4[0] + b0v), softplusf(acc4[1] + b1v));
                *(float2*)(C + (size_t)(row + 8) * ldc + col) =
                    make_float2(softplusf(acc4[2] + b0v), softplusf(acc4[3] + b1v));
            } else {
                if (col < n_real) {   // col even, n_real even -> covers col+1
                    atomicAdd(&C[(size_t)row * ldc + col],       acc4[0]);
                    atomicAdd(&C[(size_t)row * ldc + col + 1],   acc4[1]);
                    atomicAdd(&C[(size_t)(row + 8) * ldc + col],     acc4[2]);
                    atomicAdd(&C[(size_t)(row + 8) * ldc + col + 1], acc4[3]);
                }
            }
        }
    }
}

// ---------------------------------------------------------------------------
// Launch. Inputs: x, h, W_xproj, W_dt, b_dt, A_log, D, W_out.
// Output: [y (1024*4096), h_new (1024*4096*16)].
// ---------------------------------------------------------------------------
extern "C" void kernel_launch(void* const* d_in, const int* in_sizes, int n_in,
                              void* d_out, int out_size)
{
    const float* x    = (const float*)d_in[0];
    const float* h    = (const float*)d_in[1];
    const float* Wxp  = (const float*)d_in[2];
    const float* Wdt  = (const float*)d_in[3];
    const float* bdt  = (const float*)d_in[4];
    const float* Alog = (const float*)d_in[5];
    const float* Dv   = (const float*)d_in[6];
    const float* Wout = (const float*)d_in[7];

    float* y_out    = (float*)d_out;
    float* hnew_out = y_out + (size_t)BATCH * D_MODEL;

    float *xp_p, *delta_p;
    uint16_t *Wh16_p, *Yh_p, *xh_p, *xl_p, *Wxh_p, *Wxl_p, *dh_p, *dl_p, *Wdh_p, *Wdl_p;
    cudaGetSymbolAddress((void**)&xp_p, g_xp);
    cudaGetSymbolAddress((void**)&delta_p, g_delta);
    cudaGetSymbolAddress((void**)&Wh16_p, g_Wh16);
    cudaGetSymbolAddress((void**)&Yh_p, g_Yh);
    cudaGetSymbolAddress((void**)&xh_p, g_xh);
    cudaGetSymbolAddress((void**)&xl_p, g_xl);
    cudaGetSymbolAddress((void**)&Wxh_p, g_Wxh);
    cudaGetSymbolAddress((void**)&Wxl_p, g_Wxl);
    cudaGetSymbolAddress((void**)&dh_p, g_dh);
    cudaGetSymbolAddress((void**)&dl_p, g_dl);
    cudaGetSymbolAddress((void**)&Wdh_p, g_Wdh);
    cudaGetSymbolAddress((void**)&Wdl_p, g_Wdl);

    const int SMEM4 = 2 * 4 * TILE_B;   // 81920  (bf16x3: 4 tiles, 2 stages)
    const int SMEM2 = 4 * 2 * TILE_B;   // 81920  (fp16x1: 2 tiles, 4 stages)
    cudaFuncSetAttribute((const void*)gemm16<0, true, true, 2, 2, 2>,
                         cudaFuncAttributeMaxDynamicSharedMemorySize, SMEM4);
    cudaFuncSetAttribute((const void*)gemm16<0, true, true, 1, 2, 2>,
                         cudaFuncAttributeMaxDynamicSharedMemorySize, SMEM4);
    cudaFuncSetAttribute((const void*)gemm16<1, false, false, 0, 4, 2>,
                         cudaFuncAttributeMaxDynamicSharedMemorySize, SMEM2);

    // Operand preparation
    conv_fp16_k<<<(D_MODEL * D_MODEL) / (4 * 256), 256>>>(Wout, Wh16_p);
    split_bf16_k<<<(BATCH * D_MODEL) / (4 * 256), 256>>>(x, xh_p, xl_p);
    split_wxproj_k<<<(WXP_PAD * D_MODEL) / (4 * 256), 256>>>(Wxp);
    split_bf16_k<<<(D_MODEL * DT_RANK) / (4 * 256), 256>>>(Wdt, Wdh_p, Wdl_p);
    zero_xp_kernel<<<(BATCH * XP_COLS + 255) / 256, 256>>>();

    // G1: xp = x @ W_xproj^T  (bf16x3 HMMA, split-K=8, 2-stage, occ 2 -> 1 wave)
    gemm16<0, true, true, 2, 2, 2><<<dim3(BATCH / 128, WXP_PAD / 128, 8), 256, SMEM4>>>(
        xh_p, xl_p, Wxh_p, Wxl_p, xp_p, XP_COLS, D_MODEL, (D_MODEL / 8) / 32,
        nullptr, XP_COLS);

    // delta_raw split (xp cols 0..255 -> bf16 hi/lo)
    split_xp_k<<<(BATCH * DT_RANK) / (4 * 256), 256>>>();

    // G2: delta = softplus(delta_raw @ W_dt^T + b_dt)  (bf16x3, 2-stage, occ 2)
    gemm16<0, true, true, 1, 2, 2><<<dim3(BATCH / 128, D_MODEL / 128, 1), 256, SMEM4>>>(
        dh_p, dl_p, Wdh_p, Wdl_p, delta_p, D_MODEL, DT_RANK, DT_RANK / 32,
        bdt, D_MODEL);

    // Standalone state update
    state_update<<<dim3(D_MODEL / 256, BATCH), 256>>>(x, h, Alog, Dv, hnew_out);

    // G3: y = fp16(ypre) @ fp16(W_out)^T  (single product, 4-stage, occ 2)
    gemm16<1, false, false, 0, 4, 2><<<dim3(BATCH / 128, D_MODEL / 128, 1), 256, SMEM2>>>(
        Yh_p, nullptr, Wh16_p, nullptr, y_out, D_MODEL, D_MODEL, D_MODEL / 32,
        nullptr, D_MODEL);
}

// round 12
// speedup vs baseline: 1.5142x; 1.0021x over previous
#include <cuda_runtime.h>
#include <cuda_bf16.h>
#include <cuda_fp16.h>
#include <math.h>
#include <stdint.h>

#define BATCH   1024
#define D_MODEL 4096
#define D_STATE 16
#define DT_RANK 256
#define XP_COLS (DT_RANK + 2 * D_STATE)   // 288
#define WXP_PAD 384                        // 288 padded to 3 x 128

// ---------------- scratch (allocation-free rule: __device__ globals) --------
__device__ float g_xp[BATCH * XP_COLS];
__device__ float g_delta[BATCH * D_MODEL];
__device__ uint16_t g_Wh16[(size_t)D_MODEL * D_MODEL];   // fp16(W_out)
__device__ uint16_t g_Yh[(size_t)BATCH * D_MODEL];       // fp16(ypre)
__device__ uint16_t g_xh[(size_t)BATCH * D_MODEL];       // bf16 hi(x)
__device__ uint16_t g_xl[(size_t)BATCH * D_MODEL];       // bf16 lo(x)
__device__ uint16_t g_Wxh[(size_t)WXP_PAD * D_MODEL];    // bf16 hi(W_xproj), padded
__device__ uint16_t g_Wxl[(size_t)WXP_PAD * D_MODEL];
__device__ uint16_t g_dh[(size_t)BATCH * DT_RANK];       // bf16 hi(delta_raw)
__device__ uint16_t g_dl[(size_t)BATCH * DT_RANK];
__device__ uint16_t g_Wdh[(size_t)D_MODEL * DT_RANK];    // bf16 hi(W_dt)
__device__ uint16_t g_Wdl[(size_t)D_MODEL * DT_RANK];

__device__ __forceinline__ float softplusf(float z) {
    return (z > 20.0f) ? z : log1pf(__expf(z));
}

// ---------------- PTX helpers (sm_80-class only; no 'a'-target features) ----
__device__ __forceinline__ uint32_t smem_u32(const void* p) {
    uint32_t a;
    asm("{ .reg .u64 t; cvta.to.shared.u64 t, %1; cvt.u32.u64 %0, t; }" : "=r"(a) : "l"(p));
    return a;
}
__device__ __forceinline__ void cpasync16(uint32_t dst, const void* src) {
    asm volatile("cp.async.cg.shared.global [%0], [%1], 16;" :: "r"(dst), "l"(src));
}
__device__ __forceinline__ void cpasync_commit() {
    asm volatile("cp.async.commit_group;" ::: "memory");
}
__device__ __forceinline__ void ldmatrix_x4(uint32_t* r, uint32_t addr) {
    asm volatile("ldmatrix.sync.aligned.m8n8.x4.shared.b16 {%0,%1,%2,%3}, [%4];"
                 : "=r"(r[0]), "=r"(r[1]), "=r"(r[2]), "=r"(r[3]) : "r"(addr));
}
// DT: 0 = bf16, 1 = fp16
template<int DT>
__device__ __forceinline__ void mma16(float* c, const uint32_t* a, const uint32_t* b) {
    if constexpr (DT == 0) {
        asm volatile(
            "mma.sync.aligned.m16n8k16.row.col.f32.bf16.bf16.f32 "
            "{%0,%1,%2,%3}, {%4,%5,%6,%7}, {%8,%9}, {%0,%1,%2,%3};"
            : "+f"(c[0]), "+f"(c[1]), "+f"(c[2]), "+f"(c[3])
            : "r"(a[0]), "r"(a[1]), "r"(a[2]), "r"(a[3]), "r"(b[0]), "r"(b[1]));
    } else {
        asm volatile(
            "mma.sync.aligned.m16n8k16.row.col.f32.f16.f16.f32 "
            "{%0,%1,%2,%3}, {%4,%5,%6,%7}, {%8,%9}, {%0,%1,%2,%3};"
            : "+f"(c[0]), "+f"(c[1]), "+f"(c[2]), "+f"(c[3])
            : "r"(a[0]), "r"(a[1]), "r"(a[2]), "r"(a[3]), "r"(b[0]), "r"(b[1]));
    }
}

// ---------------------------------------------------------------------------
// Conversion / split kernels (measured-good configuration)
// ---------------------------------------------------------------------------
__global__ void zero_xp_kernel() {
    int i = blockIdx.x * blockDim.x + threadIdx.x;
    if (i < BATCH * XP_COLS) g_xp[i] = 0.0f;
}

__device__ __forceinline__ void split4_bf16(const float* vv, uint16_t* h, uint16_t* l, size_t i) {
    #pragma unroll
    for (int q = 0; q < 4; q++) {
        __nv_bfloat16 hi = __float2bfloat16(vv[q]);
        __nv_bfloat16 lo = __float2bfloat16(vv[q] - __bfloat162float(hi));
        h[i + q] = *(uint16_t*)&hi;
        l[i + q] = *(uint16_t*)&lo;
    }
}

__global__ void __launch_bounds__(256)
split_bf16_k(const float* __restrict__ in, uint16_t* __restrict__ h, uint16_t* __restrict__ l) {
    size_t i = ((size_t)blockIdx.x * blockDim.x + threadIdx.x) * 4;
    float4 v = *(const float4*)(in + i);
    float vv[4] = {v.x, v.y, v.z, v.w};
    split4_bf16(vv, h, l, i);
}

__global__ void __launch_bounds__(256)
conv_fp16_k(const float* __restrict__ in, uint16_t* __restrict__ out) {
    size_t i = ((size_t)blockIdx.x * blockDim.x + threadIdx.x) * 4;
    float4 v = *(const float4*)(in + i);
    __half h0 = __float2half_rn(v.x), h1 = __float2half_rn(v.y);
    __half h2 = __float2half_rn(v.z), h3 = __float2half_rn(v.w);
    uint16_t* o = out + i;
    o[0] = *(uint16_t*)&h0; o[1] = *(uint16_t*)&h1;
    o[2] = *(uint16_t*)&h2; o[3] = *(uint16_t*)&h3;
}

__global__ void __launch_bounds__(256)
split_wxproj_k(const float* __restrict__ in) {
    size_t i = ((size_t)blockIdx.x * blockDim.x + threadIdx.x) * 4;   // over 384*4096
    int row = (int)(i >> 12);
    float vv[4] = {0.f, 0.f, 0.f, 0.f};
    if (row < XP_COLS) {
        float4 v = *(const float4*)(in + i);
        vv[0] = v.x; vv[1] = v.y; vv[2] = v.z; vv[3] = v.w;
    }
    split4_bf16(vv, g_Wxh, g_Wxl, i);
}

__global__ void __launch_bounds__(256)
split_xp_k() {
    size_t i = ((size_t)blockIdx.x * blockDim.x + threadIdx.x) * 4;   // over 1024*256
    int row = (int)(i >> 8);
    int col = (int)(i & 255);
    float4 v = *(const float4*)(g_xp + (size_t)row * XP_COLS + col);
    float vv[4] = {v.x, v.y, v.z, v.w};
    split4_bf16(vv, g_dh, g_dl, i);
}

// ---------------------------------------------------------------------------
// Standalone fused state update, 2 d-values per thread (MLP 4 -> 8).
// Grid (8, 1024) = 8192 CTAs. No cache hints (measured-bad).
// ---------------------------------------------------------------------------
__global__ void __launch_bounds__(256)
state_update(const float* __restrict__ x,
             const float* __restrict__ h,
             const float* __restrict__ A_log,
             const float* __restrict__ Dv,
             float* __restrict__ h_new)
{
    __shared__ float sA[D_STATE], sB[D_STATE], sC[D_STATE];
    const int b = blockIdx.y;
    const int d0 = blockIdx.x * 512 + threadIdx.x;

    if (threadIdx.x < D_STATE) {
        int n = threadIdx.x;
        sA[n] = -expf(A_log[n]);
        sB[n] = g_xp[(size_t)b * XP_COLS + DT_RANK + n];
        sC[n] = g_xp[(size_t)b * XP_COLS + DT_RANK + D_STATE + n];
    }
    __syncthreads();

    const size_t bd0 = (size_t)b * D_MODEL + d0;
    const size_t bd1 = bd0 + 256;

    const float delta0 = g_delta[bd0];
    const float delta1 = g_delta[bd1];
    const float xv0 = x[bd0];
    const float xv1 = x[bd1];
    const float Dv0 = Dv[d0];
    const float Dv1 = Dv[d0 + 256];

    // 8 independent 16B loads in flight
    const float4* hp0 = (const float4*)(h + bd0 * D_STATE);
    const float4* hp1 = (const float4*)(h + bd1 * D_STATE);
    float4 hv0[4], hv1[4];
    #pragma unroll
    for (int q = 0; q < 4; q++) hv0[q] = hp0[q];
    #pragma unroll
    for (int q = 0; q < 4; q++) hv1[q] = hp1[q];

    float4* hop0 = (float4*)(h_new + bd0 * D_STATE);
    float4* hop1 = (float4*)(h_new + bd1 * D_STATE);

    const float dx0 = delta0 * xv0;
    const float dx1 = delta1 * xv1;
    float acc0 = 0.0f, acc1 = 0.0f;
    #pragma unroll
    for (int q = 0; q < 4; q++) {
        float a0 = sA[4 * q + 0], a1 = sA[4 * q + 1], a2 = sA[4 * q + 2], a3 = sA[4 * q + 3];
        float B0 = sB[4 * q + 0], B1 = sB[4 * q + 1], B2 = sB[4 * q + 2], B3 = sB[4 * q + 3];
        float C0 = sC[4 * q + 0], C1 = sC[4 * q + 1], C2 = sC[4 * q + 2], C3 = sC[4 * q + 3];

        float u0 = __expf(delta0 * a0) * hv0[q].x + dx0 * B0;
        float u1 = __expf(delta0 * a1) * hv0[q].y + dx0 * B1;
        float u2 = __expf(delta0 * a2) * hv0[q].z + dx0 * B2;
        float u3 = __expf(delta0 * a3) * hv0[q].w + dx0 * B3;
        acc0 += C0 * u0 + C1 * u1 + C2 * u2 + C3 * u3;
        hop0[q] = make_float4(u0, u1, u2, u3);

        float w0 = __expf(delta1 * a0) * hv1[q].x + dx1 * B0;
        float w1 = __expf(delta1 * a1) * hv1[q].y + dx1 * B1;
        float w2 = __expf(delta1 * a2) * hv1[q].z + dx1 * B2;
        float w3 = __expf(delta1 * a3) * hv1[q].w + dx1 * B3;
        acc1 += C0 * w0 + C1 * w1 + C2 * w2 + C3 * w3;
        hop1[q] = make_float4(w0, w1, w2, w3);
    }
    float yp0 = acc0 + Dv0 * xv0;
    float yp1 = acc1 + Dv1 * xv1;
    __half hh0 = __float2half_rn(yp0);
    __half hh1 = __float2half_rn(yp1);
    g_Yh[bd0] = *(uint16_t*)&hh0;
    g_Yh[bd1] = *(uint16_t*)&hh1;
}

// ---------------------------------------------------------------------------
// Unified HMMA GEMM: C[m,n] (+)= sum_k A[m,k]*B[n,k], 16-bit operands.
//   ASPLIT: A = Ah + Al. BSPLIT: adds Ah*Bl cross term.
// CTA 128x128, BK=32, 8 warps (2Mx4N), warp tile 64x32. 80B-padded SMEM rows.
// EPI: 0 = plain store, 1 = softplus(acc+bias[col]) store, 2 = guarded atomicAdd.
// OCC: min blocks/SM (2 -> <=128 regs, co-resident CTAs, single wave).
// ---------------------------------------------------------------------------
#define ROW_B 80
#define TILE_B (128 * ROW_B)          // 10240

template<int DT, bool ASPLIT, bool BSPLIT, int EPI, int NSTAGE, int OCC>
__global__ void __launch_bounds__(256, OCC)
gemm16(const uint16_t* __restrict__ Ah, const uint16_t* __restrict__ Al,
       const uint16_t* __restrict__ Bh, const uint16_t* __restrict__ Bl,
       float* __restrict__ C, int ldc, int ldab, int niters,
       const float* __restrict__ bias, int n_real)
{
    constexpr int NTILES = 1 + (ASPLIT ? 1 : 0) + 1 + (BSPLIT ? 1 : 0);
    constexpr uint32_t OFF_A0 = 0;
    constexpr uint32_t OFF_A1 = ASPLIT ? TILE_B : 0;
    constexpr uint32_t OFF_B0 = (ASPLIT ? 2 : 1) * TILE_B;
    constexpr uint32_t OFF_B1 = (ASPLIT ? 3 : 2) * TILE_B;   // only if BSPLIT
    constexpr uint32_t STAGE = NTILES * TILE_B;

    extern __shared__ char smem[];
    const uint32_t sb = smem_u32(smem);
    const int tid = threadIdx.x;
    const int wid = tid >> 5;
    const int lane = tid & 31;
    const int warp_m = wid >> 2;
    const int warp_n = wid & 3;
    const int bm = blockIdx.x * 128;
    const int bn = blockIdx.y * 128;
    const int k_begin = blockIdx.z * niters * 32;

    auto load_stage = [&](uint32_t st, int k0) {
        #pragma unroll
        for (int cc = 0; cc < 2; cc++) {
            const int idx = tid + 256 * cc;
            const int row = idx >> 2;
            const int ch  = idx & 3;
            const uint32_t d = st + (uint32_t)(row * ROW_B + ch * 16);
            const int gk = k0 + ch * 8;
            cpasync16(d + OFF_A0, Ah + (size_t)(bm + row) * ldab + gk);
            if constexpr (ASPLIT)
                cpasync16(d + OFF_A1, Al + (size_t)(bm + row) * ldab + gk);
            cpasync16(d + OFF_B0, Bh + (size_t)(bn + row) * ldab + gk);
            if constexpr (BSPLIT)
                cpasync16(d + OFF_B1, Bl + (size_t)(bn + row) * ldab + gk);
        }
        cpasync_commit();
    };

    // ldmatrix per-lane byte offsets (within a tile, ks=0)
    uint32_t aoff[4], boff[2];
    #pragma unroll
    for (int mi = 0; mi < 4; mi++)
        aoff[mi] = (uint32_t)((warp_m * 64 + mi * 16 + (lane & 15)) * ROW_B + (lane >> 4) * 16);
    #pragma unroll
    for (int pi = 0; pi < 2; pi++) {
        int chunk = lane >> 3;
        int n = warp_n * 32 + pi * 16 + (chunk >> 1) * 8 + (lane & 7);
        boff[pi] = (uint32_t)(n * ROW_B + (chunk & 1) * 16);
    }

    float acc[4][4][4];
    #pragma unroll
    for (int mi = 0; mi < 4; mi++)
        #pragma unroll
        for (int ni = 0; ni < 4; ni++)
            #pragma unroll
            for (int q = 0; q < 4; q++) acc[mi][ni][q] = 0.0f;

    // prologue: stages 0..NSTAGE-2
    #pragma unroll
    for (int s = 0; s < NSTAGE - 1; s++)
        load_stage(sb + s * STAGE, k_begin + s * 32);

    for (int it = 0; it < niters; it++) {
        if (it + NSTAGE - 1 < niters)
            load_stage(sb + ((it + NSTAGE - 1) % NSTAGE) * STAGE,
                       k_begin + (it + NSTAGE - 1) * 32);
        else
            cpasync_commit();   // keep group count uniform
        asm volatile("cp.async.wait_group %0;" :: "n"(NSTAGE - 1) : "memory");
        __syncthreads();

        const uint32_t st = sb + (it % NSTAGE) * STAGE;
        #pragma unroll
        for (int ks = 0; ks < 2; ks++) {
            uint32_t a0[4][4], a1[4][4], b0[2][4], b1[2][4];
            #pragma unroll
            for (int mi = 0; mi < 4; mi++) {
                ldmatrix_x4(a0[mi], st + OFF_A0 + aoff[mi] + ks * 32);
                if constexpr (ASPLIT)
                    ldmatrix_x4(a1[mi], st + OFF_A1 + aoff[mi] + ks * 32);
            }
            #pragma unroll
            for (int pi = 0; pi < 2; pi++) {
                ldmatrix_x4(b0[pi], st + OFF_B0 + boff[pi] + ks * 32);
                if constexpr (BSPLIT)
                    ldmatrix_x4(b1[pi], st + OFF_B1 + boff[pi] + ks * 32);
            }
            #pragma unroll
            for (int mi = 0; mi < 4; mi++) {
                #pragma unroll
                for (int ni = 0; ni < 4; ni++) {
                    const int pi = ni >> 1;
                    const int sel = (ni & 1) * 2;
                    uint32_t bh[2] = {b0[pi][sel], b0[pi][sel + 1]};
                    mma16<DT>(acc[mi][ni], a0[mi], bh);
                    if constexpr (ASPLIT)
                        mma16<DT>(acc[mi][ni], a1[mi], bh);
                    if constexpr (BSPLIT) {
                        uint32_t bl[2] = {b1[pi][sel], b1[pi][sel + 1]};
                        mma16<DT>(acc[mi][ni], a0[mi], bl);
                    }
                }
            }
        }
        __syncthreads();
    }

    // epilogue
    #pragma unroll
    for (int mi = 0; mi < 4; mi++) {
        const int row = bm + warp_m * 64 + mi * 16 + (lane >> 2);
        #pragma unroll
        for (int ni = 0; ni < 4; ni++) {
            const int col = bn + warp_n * 32 + ni * 8 + (lane & 3) * 2;
            float* acc4 = acc[mi][ni];
            if constexpr (EPI == 0) {
                *(float2*)(C + (size_t)row * ldc + col) = make_float2(acc4[0], acc4[1]);
                *(float2*)(C + (size_t)(row + 8) * ldc + col) = make_float2(acc4[2], acc4[3]);
            } else if constexpr (EPI == 1) {
                float b0v = bias[col], b1v = bias[col + 1];
                *(float2*)(C + (size_t)row * ldc + col) =
                    make_float2(softplusf(acc4[0] + b0v), softplusf(acc4[1] + b1v));
                *(float2*)(C + (size_t)(row + 8) * ldc + col) =
                    make_float2(softplusf(acc4[2] + b0v), softplusf(acc4[3] + b1v));
            } else {
                if (col < n_real) {   // col even, n_real even -> covers col+1
                    atomicAdd(&C[(size_t)row * ldc + col],       acc4[0]);
                    atomicAdd(&C[(size_t)row * ldc + col + 1],   acc4[1]);
                    atomicAdd(&C[(size_t)(row + 8) * ldc + col],     acc4[2]);
                    atomicAdd(&C[(size_t)(row + 8) * ldc + col + 1], acc4[3]);
                }
            }
        }
    }
}

// ---------------------------------------------------------------------------
// Launch. Inputs: x, h, W_xproj, W_dt, b_dt, A_log, D, W_out.
// Output: [y (1024*4096), h_new (1024*4096*16)].
// ---------------------------------------------------------------------------
extern "C" void kernel_launch(void* const* d_in, const int* in_sizes, int n_in,
                              void* d_out, int out_size)
{
    const float* x    = (const float*)d_in[0];
    const float* h    = (const float*)d_in[1];
    const float* Wxp  = (const float*)d_in[2];
    const float* Wdt  = (const float*)d_in[3];
    const float* bdt  = (const float*)d_in[4];
    const float* Alog = (const float*)d_in[5];
    const float* Dv   = (const float*)d_in[6];
    const float* Wout = (const float*)d_in[7];

    float* y_out    = (float*)d_out;
    float* hnew_out = y_out + (size_t)BATCH * D_MODEL;

    float *xp_p, *delta_p;
    uint16_t *Wh16_p, *Yh_p, *xh_p, *xl_p, *Wxh_p, *Wxl_p, *dh_p, *dl_p, *Wdh_p, *Wdl_p;
    cudaGetSymbolAddress((void**)&xp_p, g_xp);
    cudaGetSymbolAddress((void**)&delta_p, g_delta);
    cudaGetSymbolAddress((void**)&Wh16_p, g_Wh16);
    cudaGetSymbolAddress((void**)&Yh_p, g_Yh);
    cudaGetSymbolAddress((void**)&xh_p, g_xh);
    cudaGetSymbolAddress((void**)&xl_p, g_xl);
    cudaGetSymbolAddress((void**)&Wxh_p, g_Wxh);
    cudaGetSymbolAddress((void**)&Wxl_p, g_Wxl);
    cudaGetSymbolAddress((void**)&dh_p, g_dh);
    cudaGetSymbolAddress((void**)&dl_p, g_dl);
    cudaGetSymbolAddress((void**)&Wdh_p, g_Wdh);
    cudaGetSymbolAddress((void**)&Wdl_p, g_Wdl);

    const int SMEM4 = 2 * 4 * TILE_B;   // 81920  (bf16x3: 4 tiles, 2 stages)
    const int SMEM2 = 4 * 2 * TILE_B;   // 81920  (fp16x1: 2 tiles, 4 stages)
    cudaFuncSetAttribute((const void*)gemm16<0, true, true, 2, 2, 2>,
                         cudaFuncAttributeMaxDynamicSharedMemorySize, SMEM4);
    cudaFuncSetAttribute((const void*)gemm16<0, true, true, 1, 2, 2>,
                         cudaFuncAttributeMaxDynamicSharedMemorySize, SMEM4);
    cudaFuncSetAttribute((const void*)gemm16<1, false, false, 0, 4, 2>,
                         cudaFuncAttributeMaxDynamicSharedMemorySize, SMEM2);

    // Operand preparation
    conv_fp16_k<<<(D_MODEL * D_MODEL) / (4 * 256), 256>>>(Wout, Wh16_p);
    split_bf16_k<<<(BATCH * D_MODEL) / (4 * 256), 256>>>(x, xh_p, xl_p);
    split_wxproj_k<<<(WXP_PAD * D_MODEL) / (4 * 256), 256>>>(Wxp);
    split_bf16_k<<<(D_MODEL * DT_RANK) / (4 * 256), 256>>>(Wdt, Wdh_p, Wdl_p);
    zero_xp_kernel<<<(BATCH * XP_COLS + 255) / 256, 256>>>();

    // G1: xp = x @ W_xproj^T  (bf16x3 HMMA, split-K=8, 2-stage, occ 2 -> 1 wave)
    gemm16<0, true, true, 2, 2, 2><<<dim3(BATCH / 128, WXP_PAD / 128, 8), 256, SMEM4>>>(
        xh_p, xl_p, Wxh_p, Wxl_p, xp_p, XP_COLS, D_MODEL, (D_MODEL / 8) / 32,
        nullptr, XP_COLS);

    // delta_raw split (xp cols 0..255 -> bf16 hi/lo)
    split_xp_k<<<(BATCH * DT_RANK) / (4 * 256), 256>>>();

    // G2: delta = softplus(delta_raw @ W_dt^T + b_dt)  (bf16x3, 2-stage, occ 2)
    gemm16<0, true, true, 1, 2, 2><<<dim3(BATCH / 128, D_MODEL / 128, 1), 256, SMEM4>>>(
        dh_p, dl_p, Wdh_p, Wdl_p, delta_p, D_MODEL, DT_RANK, DT_RANK / 32,
        bdt, D_MODEL);

    // Standalone state update (2 d per thread -> MLP 8)
    state_update<<<dim3(D_MODEL / 512, BATCH), 256>>>(x, h, Alog, Dv, hnew_out);

    // G3: y = fp16(ypre) @ fp16(W_out)^T  (single product, 4-stage, occ 2)
    gemm16<1, false, false, 0, 4, 2><<<dim3(BATCH / 128, D_MODEL / 128, 1), 256, SMEM2>>>(
        Yh_p, nullptr, Wh16_p, nullptr, y_out, D_MODEL, D_MODEL, D_MODEL / 32,
        nullptr, D_MODEL);
}